// round 10
// baseline (speedup 1.0000x reference)
#include <cuda_runtime.h>
#include <cstdint>

// ---------------- problem constants ----------------------------------------
#define Bq     16
#define NSEQ   1569            // 1 + 8*196
#define DMODEL 768
#define NH     12
#define DH     64
#define NF     8
#define NPF    196
#define MROWS  (Bq * NSEQ)     // 25104
#define QKVC   (3 * DMODEL)    // 2304

// scratch (no cudaMalloc allowed)
__device__ float g_qkv[(size_t)MROWS * QKVC];     // 231 MB
__device__ float g_attn[(size_t)MROWS * DMODEL];  // 77 MB  (canonical layout)
__device__ float g_x[(size_t)MROWS * DMODEL];     // rounded x, k-pair packed
__device__ float g_wq[(size_t)DMODEL * QKVC];     // rounded w_qkv, [N][K] packed
__device__ float g_wp[(size_t)DMODEL * DMODEL];   // rounded w_proj, [N][K] packed

__device__ __forceinline__ uint32_t f2tf(float x) {
    uint32_t r;
    asm("cvt.rna.tf32.f32 %0, %1;" : "=r"(r) : "f"(x));
    return r;
}
__device__ __forceinline__ float f2tff(float x) { return __uint_as_float(f2tf(x)); }

__device__ __forceinline__ uint32_t s2u(const void* p) {
    return (uint32_t)__cvta_generic_to_shared(p);
}

#define MMA_TF32(c, a0,a1,a2,a3, b0,b1)                                          \
    asm volatile(                                                                 \
        "mma.sync.aligned.m16n8k8.row.col.f32.tf32.tf32.f32 "                     \
        "{%0,%1,%2,%3}, {%4,%5,%6,%7}, {%8,%9}, {%0,%1,%2,%3};"                   \
        : "+f"(c[0]), "+f"(c[1]), "+f"(c[2]), "+f"(c[3])                          \
        : "r"(a0), "r"(a1), "r"(a2), "r"(a3), "r"(b0), "r"(b1))

#define LDS64(lo, hi, addr)                                                      \
    asm volatile("ld.shared.v2.u32 {%0,%1}, [%2];"                               \
        : "=r"(lo), "=r"(hi) : "r"(addr))

// ---------------- prep: round + k-pair pack ---------------------------------
// Each 8-float k-block [a0..a7] -> [a0,a4,a1,a5,a2,a6,a3,a7] so that the mma
// fragment pair (k, k+4) is adjacent in memory (enables LDS.64 fragments).
__global__ __launch_bounds__(256) void round_pack(
    const float* __restrict__ in, float* __restrict__ out, int n8)
{
    int i = blockIdx.x * 256 + threadIdx.x;
    if (i < n8) {
        const float4* ip = reinterpret_cast<const float4*>(in) + i * 2;
        float4 v0 = ip[0], v1 = ip[1];
        float4 o0, o1;
        o0.x = f2tff(v0.x); o0.y = f2tff(v1.x); o0.z = f2tff(v0.y); o0.w = f2tff(v1.y);
        o1.x = f2tff(v0.z); o1.y = f2tff(v1.z); o1.z = f2tff(v0.w); o1.w = f2tff(v1.w);
        float4* op = reinterpret_cast<float4*>(out) + i * 2;
        op[0] = o0; op[1] = o1;
    }
}

// ---------------- prep: round + transpose + k-pair pack ---------------------
__global__ __launch_bounds__(256) void transpose_pack(
    const float* __restrict__ in, float* __restrict__ out, int R, int C)
{
    __shared__ float t[32][33];
    const int bx = blockIdx.x * 32;   // C offset
    const int by = blockIdx.y * 32;   // R offset (k)
    const int tx = threadIdx.x & 31, ty = threadIdx.x >> 5;  // 32 x 8
#pragma unroll
    for (int j = 0; j < 4; j++)
        t[ty + j * 8][tx] = f2tff(in[(long)(by + ty + j * 8) * C + bx + tx]);
    __syncthreads();
    const int kr = tx & 7;
    const int kp = (tx & ~7) | ((kr & 3) * 2 + (kr >> 2));
#pragma unroll
    for (int j = 0; j < 4; j++)
        out[(long)(bx + ty + j * 8) * R + by + kp] = t[tx][ty + j * 8];
}

// ---------------- TF32 GEMM: cp.async 3-stage -------------------------------
// B [N][K] k-pair packed always (LDS.64 fragments). A is k-pair packed when
// APK=true (LDS.64) or canonical when APK=false (scalar LDS, round-6 proven).
#define BM 128
#define BN 128
#define BK 32
#define TSTR 36
#define TBUF (128 * TSTR)
#define STAGES 3
#define GEMM_SMEM (STAGES * 2 * TBUF * 4)   // 110592 bytes

template <bool BIAS, bool APK>
__global__ __launch_bounds__(256, 2) void gemm_tf32_pk(
    const float* __restrict__ A, const float* __restrict__ Bt,
    const float* __restrict__ bias, float* __restrict__ C,
    int Mr, int Nc, int Kd)
{
    extern __shared__ float sm[];
    float* As = sm;
    float* Bs = sm + STAGES * TBUF;

    const int tid  = threadIdx.x;
    const int warp = tid >> 5, lane = tid & 31;
    const int gid  = lane >> 2, tig = lane & 3;
    const int wm   = (warp >> 1) * 32;    // 4 warps along M
    const int wn   = (warp & 1) * 64;     // 2 warps along N
    const int brow = blockIdx.y * BM;
    const int bcol = blockIdx.x * BN;

    float acc[2][8][4];
#pragma unroll
    for (int mi = 0; mi < 2; mi++)
#pragma unroll
        for (int ni = 0; ni < 8; ni++)
#pragma unroll
            for (int r = 0; r < 4; r++) acc[mi][ni][r] = 0.f;

    const int nkt = Kd / BK;

    auto issue = [&](int kt) {
        const int buf = kt % STAGES;
        float* Ab = As + buf * TBUF;
        float* Bb = Bs + buf * TBUF;
#pragma unroll
        for (int i = 0; i < 4; i++) {
            int cid = tid + i * 256;
            int row = cid >> 3, c4 = (cid & 7) << 2;
            const float* src = A + (long)(brow + row) * Kd + kt * BK + c4;
            int sz = (brow + row < Mr) ? 16 : 0;
            asm volatile("cp.async.cg.shared.global [%0], [%1], 16, %2;"
                         :: "r"(s2u(Ab + row * TSTR + c4)), "l"(src), "r"(sz));
        }
#pragma unroll
        for (int i = 0; i < 4; i++) {
            int cid = tid + i * 256;
            int row = cid >> 3, c4 = (cid & 7) << 2;
            const float* src = Bt + (long)(bcol + row) * Kd + kt * BK + c4;
            asm volatile("cp.async.cg.shared.global [%0], [%1], 16;"
                         :: "r"(s2u(Bb + row * TSTR + c4)), "l"(src));
        }
    };

    auto compute = [&](int buf) {
        const float* Ab = As + buf * TBUF;
        const float* Bb = Bs + buf * TBUF;
        const uint32_t bb = s2u(Bb + (wn + gid) * TSTR + 2 * tig);
        // A bases: packed uses adjacent (k, k+4) pairs; canonical uses scalars
        const uint32_t a0p = s2u(Ab + (wm      + gid) * TSTR + 2 * tig);
        const uint32_t a1p = s2u(Ab + (wm + 8  + gid) * TSTR + 2 * tig);
        const uint32_t a2p = s2u(Ab + (wm + 16 + gid) * TSTR + 2 * tig);
        const uint32_t a3p = s2u(Ab + (wm + 24 + gid) * TSTR + 2 * tig);
        const uint32_t* Ab32 = reinterpret_cast<const uint32_t*>(Ab);
#pragma unroll
        for (int ks = 0; ks < 4; ks++) {
            const uint32_t kb = ks * 32;   // k8-step byte offset
            uint32_t af[2][4], bf[8][2];
            if (APK) {
                LDS64(af[0][0], af[0][2], a0p + kb);
                LDS64(af[0][1], af[0][3], a1p + kb);
                LDS64(af[1][0], af[1][2], a2p + kb);
                LDS64(af[1][1], af[1][3], a3p + kb);
            } else {
                const int k0 = ks * 8;
#pragma unroll
                for (int mi = 0; mi < 2; mi++) {
                    const uint32_t* p = Ab32 + (wm + mi * 16 + gid) * TSTR + k0 + tig;
                    af[mi][0] = p[0];
                    af[mi][1] = p[8 * TSTR];
                    af[mi][2] = p[4];
                    af[mi][3] = p[8 * TSTR + 4];
                }
            }
#pragma unroll
            for (int ni = 0; ni < 8; ni++)
                LDS64(bf[ni][0], bf[ni][1], bb + ni * (8 * TSTR * 4) + kb);
#pragma unroll
            for (int mi = 0; mi < 2; mi++)
#pragma unroll
                for (int ni = 0; ni < 8; ni++)
                    MMA_TF32(acc[mi][ni], af[mi][0], af[mi][1], af[mi][2], af[mi][3],
                             bf[ni][0], bf[ni][1]);
        }
    };

#pragma unroll
    for (int s = 0; s < STAGES - 1; s++) {
        issue(s);
        asm volatile("cp.async.commit_group;");
    }

#pragma unroll 1
    for (int kt = 0; kt < nkt; kt++) {
        asm volatile("cp.async.wait_group %0;" :: "n"(STAGES - 2));
        __syncthreads();
        compute(kt % STAGES);
        if (kt + STAGES - 1 < nkt) issue(kt + STAGES - 1);
        asm volatile("cp.async.commit_group;");
    }

#pragma unroll
    for (int mi = 0; mi < 2; mi++) {
        int r0 = brow + wm + mi * 16 + gid;
#pragma unroll
        for (int ni = 0; ni < 8; ni++) {
            int c0 = bcol + wn + ni * 8 + tig * 2;
            float bx = 0.f, by = 0.f;
            if (BIAS) { bx = bias[c0]; by = bias[c0 + 1]; }
            if (r0 < Mr) {
                float2 v = make_float2(acc[mi][ni][0] + bx, acc[mi][ni][1] + by);
                *reinterpret_cast<float2*>(C + (long)r0 * Nc + c0) = v;
            }
            if (r0 + 8 < Mr) {
                float2 v = make_float2(acc[mi][ni][2] + bx, acc[mi][ni][3] + by);
                *reinterpret_cast<float2*>(C + (long)(r0 + 8) * Nc + c0) = v;
            }
        }
    }
}

// ---------------- frame attention v3: shuffle-P, 2 CTAs/SM ------------------
#define KSTR 68
#define VSTR 72
#define F_SMEM ((200 * KSTR + 200 * VSTR) * 4)   // 112640 bytes

__global__ __launch_bounds__(256, 2) void frame_attn_mma(
    const float* __restrict__ qkv, float* __restrict__ attn)
{
    extern __shared__ float smf[];
    float* Ks = smf;              // [200][KSTR]; also Q staging scratch
    float* Vs = smf + 200 * KSTR; // [200][VSTR]

    const int tid  = threadIdx.x;
    const int warp = tid >> 5, lane = tid & 31;
    const int gid  = lane >> 2, tig = lane & 3;

    const int bid2 = blockIdx.x;
    const int half = bid2 & 1;
    const int bid  = bid2 >> 1;          // (b*NH + h)*NF + fr
    const int fr   = bid & 7;
    const int h    = (bid >> 3) % NH;
    const int b    = bid / (NF * NH);

    const int tbase  = half * 7;
    const int ntiles = half ? 6 : 7;

    const long rowbase = (long)b * NSEQ;
    const int  hoff    = h * DH;

    const uint32_t* Ku = reinterpret_cast<const uint32_t*>(Ks);
    const uint32_t* Vu = reinterpret_cast<const uint32_t*>(Vs);

    // ---- phase 1: stage this block's Q rows into Ks, coalesced ----
    const int nrows = ntiles * 16;
    for (int idx = tid; idx < nrows * 16; idx += 256) {
        int row = idx >> 4;
        int c4  = (idx & 15) << 2;
        int grow = tbase * 16 + row;
        float4 v = make_float4(0.f, 0.f, 0.f, 0.f);
        if (grow < NPF) {
            const float* qp = qkv + (rowbase + 1 + fr * NPF + grow) * QKVC + hoff + c4;
            float4 u = *reinterpret_cast<const float4*>(qp);
            v.x = f2tff(u.x * 0.125f);
            v.y = f2tff(u.y * 0.125f);
            v.z = f2tff(u.z * 0.125f);
            v.w = f2tff(u.w * 0.125f);
        }
        *reinterpret_cast<float4*>(&Ks[row * KSTR + c4]) = v;
    }
    __syncthreads();

    uint32_t af[8][4];
    if (warp < ntiles) {
        const int r0 = warp * 16 + gid;
#pragma unroll
        for (int kc = 0; kc < 8; kc++) {
            int c0 = kc * 8 + tig;
            af[kc][0] = Ku[r0 * KSTR + c0];
            af[kc][1] = Ku[(r0 + 8) * KSTR + c0];
            af[kc][2] = Ku[r0 * KSTR + c0 + 4];
            af[kc][3] = Ku[(r0 + 8) * KSTR + c0 + 4];
        }
    }
    __syncthreads();

    // ---- phase 2: load K/V (197 keys + 3 zero rows) ----
    for (int idx = tid; idx < 200 * 16; idx += 256) {
        int j  = idx >> 4;
        int c4 = (idx & 15) << 2;
        float4 kk = make_float4(0.f, 0.f, 0.f, 0.f);
        float4 vv = make_float4(0.f, 0.f, 0.f, 0.f);
        if (j < 197) {
            int t = (j == 0) ? 0 : (1 + fr * NPF + j - 1);
            const float* src = qkv + (rowbase + t) * QKVC + hoff;
            kk = *reinterpret_cast<const float4*>(src + DMODEL + c4);
            vv = *reinterpret_cast<const float4*>(src + 2 * DMODEL + c4);
            kk.x = f2tff(kk.x); kk.y = f2tff(kk.y); kk.z = f2tff(kk.z); kk.w = f2tff(kk.w);
            vv.x = f2tff(vv.x); vv.y = f2tff(vv.y); vv.z = f2tff(vv.z); vv.w = f2tff(vv.w);
        }
        *reinterpret_cast<float4*>(&Ks[j * KSTR + c4]) = kk;
        *reinterpret_cast<float4*>(&Vs[j * VSTR + c4]) = vv;
    }
    __syncthreads();

    if (warp < ntiles) {
        const int tile = tbase + warp;

        float o[8][4];
#pragma unroll
        for (int dt = 0; dt < 8; dt++)
#pragma unroll
            for (int r = 0; r < 4; r++) o[dt][r] = 0.f;
        float rs0 = 0.f, rs1 = 0.f;

        const int src0 = (lane & ~3) | (tig >> 1);
        const int src1 = src0 + 2;
        const bool oddt = (tig & 1);

#pragma unroll
        for (int chunk = 0; chunk < 5; chunk++) {
            float c[5][4];
#pragma unroll
            for (int ntl = 0; ntl < 5; ntl++)
#pragma unroll
                for (int r = 0; r < 4; r++) c[ntl][r] = 0.f;

#pragma unroll
            for (int ntl = 0; ntl < 5; ntl++) {
                const int nt = chunk * 5 + ntl;
                const uint32_t* kb = Ku + (nt * 8 + gid) * KSTR + tig;
#pragma unroll
                for (int kc = 0; kc < 8; kc++) {
                    uint32_t b0 = kb[kc * 8];
                    uint32_t b1 = kb[kc * 8 + 4];
                    MMA_TF32(c[ntl], af[kc][0], af[kc][1], af[kc][2], af[kc][3],
                             b0, b1);
                }
            }

#pragma unroll
            for (int ntl = 0; ntl < 5; ntl++) {
                const int j0 = (chunk * 5 + ntl) * 8 + tig * 2;
                float p0 = (j0     < 197) ? __expf(c[ntl][0]) : 0.f;
                float p1 = (j0 + 1 < 197) ? __expf(c[ntl][1]) : 0.f;
                float p2 = (j0     < 197) ? __expf(c[ntl][2]) : 0.f;
                float p3 = (j0 + 1 < 197) ? __expf(c[ntl][3]) : 0.f;
                rs0 += p0 + p1;
                rs1 += p2 + p3;
                c[ntl][0] = __uint_as_float(f2tf(p0));
                c[ntl][1] = __uint_as_float(f2tf(p1));
                c[ntl][2] = __uint_as_float(f2tf(p2));
                c[ntl][3] = __uint_as_float(f2tf(p3));
            }

#pragma unroll
            for (int ntl = 0; ntl < 5; ntl++) {
                const int nt = chunk * 5 + ntl;
                float x0 = __shfl_sync(0xffffffffu, c[ntl][0], src0);
                float x1 = __shfl_sync(0xffffffffu, c[ntl][1], src0);
                float x2 = __shfl_sync(0xffffffffu, c[ntl][2], src0);
                float x3 = __shfl_sync(0xffffffffu, c[ntl][3], src0);
                float y0 = __shfl_sync(0xffffffffu, c[ntl][0], src1);
                float y1 = __shfl_sync(0xffffffffu, c[ntl][1], src1);
                float y2 = __shfl_sync(0xffffffffu, c[ntl][2], src1);
                float y3 = __shfl_sync(0xffffffffu, c[ntl][3], src1);
                uint32_t a0 = __float_as_uint(oddt ? x1 : x0);
                uint32_t a1 = __float_as_uint(oddt ? x3 : x2);
                uint32_t a2 = __float_as_uint(oddt ? y1 : y0);
                uint32_t a3 = __float_as_uint(oddt ? y3 : y2);
                const uint32_t* vb = Vu + (nt * 8 + tig) * VSTR + gid;
#pragma unroll
                for (int dt = 0; dt < 8; dt++) {
                    uint32_t b0 = vb[dt * 8];
                    uint32_t b1 = vb[4 * VSTR + dt * 8];
                    MMA_TF32(o[dt], a0, a1, a2, a3, b0, b1);
                }
            }
        }

        rs0 += __shfl_xor_sync(0xffffffffu, rs0, 1);
        rs0 += __shfl_xor_sync(0xffffffffu, rs0, 2);
        rs1 += __shfl_xor_sync(0xffffffffu, rs1, 1);
        rs1 += __shfl_xor_sync(0xffffffffu, rs1, 2);
        const float inv0 = 1.f / rs0;
        const float inv1 = 1.f / rs1;

#pragma unroll
        for (int hh = 0; hh < 2; hh++) {
            int row = tile * 16 + gid + hh * 8;
            if (row < NPF) {
                float inv = hh ? inv1 : inv0;
                float* op = attn + (rowbase + 1 + fr * NPF + row) * DMODEL + hoff;
#pragma unroll
                for (int dt = 0; dt < 8; dt++) {
                    float2 v;
                    v.x = f2tff(o[dt][2 * hh]     * inv);
                    v.y = f2tff(o[dt][2 * hh + 1] * inv);
                    *reinterpret_cast<float2*>(op + dt * 8 + tig * 2) = v;
                }
            }
        }
    }
}

// ---------------- cls attention ---------------------------------------------
__global__ __launch_bounds__(256) void cls_attn(
    const float* __restrict__ qkv, float* __restrict__ attn)
{
    const int b   = blockIdx.x / NH;
    const int h   = blockIdx.x % NH;
    const int tid = threadIdx.x;

    __shared__ float qs[64];
    __shared__ float red[8][64];
    __shared__ float redl[8];

    const long rowbase = (long)b * NSEQ;
    const int  hoff    = h * DH;

    if (tid < 64) qs[tid] = qkv[rowbase * QKVC + hoff + tid] * 0.125f;
    __syncthreads();

    float acc[64];
#pragma unroll
    for (int d = 0; d < 64; d++) acc[d] = 0.f;
    float l = 0.f;

    for (int j = tid; j < NSEQ; j += 256) {
        const float* kp = qkv + (rowbase + j) * QKVC + hoff + DMODEL;
        float s0 = 0.f, s1 = 0.f, s2 = 0.f, s3 = 0.f;
#pragma unroll
        for (int d4 = 0; d4 < 16; d4++) {
            float4 kk = *reinterpret_cast<const float4*>(kp + d4 * 4);
            s0 = fmaf(qs[d4 * 4 + 0], kk.x, s0);
            s1 = fmaf(qs[d4 * 4 + 1], kk.y, s1);
            s2 = fmaf(qs[d4 * 4 + 2], kk.z, s2);
            s3 = fmaf(qs[d4 * 4 + 3], kk.w, s3);
        }
        float p = __expf((s0 + s1) + (s2 + s3));
        l += p;
        const float* vp = kp + DMODEL;
#pragma unroll
        for (int d4 = 0; d4 < 16; d4++) {
            float4 vv = *reinterpret_cast<const float4*>(vp + d4 * 4);
            acc[d4 * 4 + 0] = fmaf(p, vv.x, acc[d4 * 4 + 0]);
            acc[d4 * 4 + 1] = fmaf(p, vv.y, acc[d4 * 4 + 1]);
            acc[d4 * 4 + 2] = fmaf(p, vv.z, acc[d4 * 4 + 2]);
            acc[d4 * 4 + 3] = fmaf(p, vv.w, acc[d4 * 4 + 3]);
        }
    }

#pragma unroll
    for (int off = 16; off; off >>= 1) {
        l += __shfl_xor_sync(0xffffffffu, l, off);
#pragma unroll
        for (int d = 0; d < 64; d++)
            acc[d] += __shfl_xor_sync(0xffffffffu, acc[d], off);
    }
    const int warp = tid >> 5, lane = tid & 31;
    if (lane == 0) {
        redl[warp] = l;
#pragma unroll
        for (int d = 0; d < 64; d++) red[warp][d] = acc[d];
    }
    __syncthreads();
    if (tid < 64) {
        float s = 0.f, lt = 0.f;
#pragma unroll
        for (int w = 0; w < 8; w++) { s += red[w][tid]; lt += redl[w]; }
        attn[rowbase * DMODEL + hoff + tid] = f2tff(s / lt);
    }
}

// ---------------- host launch ----------------------------------------------
extern "C" void kernel_launch(void* const* d_in, const int* in_sizes, int n_in,
                              void* d_out, int out_size)
{
    const float* x      = (const float*)d_in[0];
    const float* w_qkv  = (const float*)d_in[1];
    const float* w_proj = (const float*)d_in[2];
    const float* b_proj = (const float*)d_in[3];
    float* out = (float*)d_out;

    float *qkv, *attn, *xr, *wq, *wp;
    cudaGetSymbolAddress((void**)&qkv,  g_qkv);
    cudaGetSymbolAddress((void**)&attn, g_attn);
    cudaGetSymbolAddress((void**)&xr,   g_x);
    cudaGetSymbolAddress((void**)&wq,   g_wq);
    cudaGetSymbolAddress((void**)&wp,   g_wp);

    cudaFuncSetAttribute((const void*)gemm_tf32_pk<false, true>,
                         cudaFuncAttributeMaxDynamicSharedMemorySize, GEMM_SMEM);
    cudaFuncSetAttribute((const void*)gemm_tf32_pk<true, false>,
                         cudaFuncAttributeMaxDynamicSharedMemorySize, GEMM_SMEM);
    cudaFuncSetAttribute(frame_attn_mma,
                         cudaFuncAttributeMaxDynamicSharedMemorySize, F_SMEM);

    // prep: round + pack x; round + transpose + pack weights to [N][K]
    {
        int n8 = (MROWS * DMODEL) / 8;
        round_pack<<<(n8 + 255) / 256, 256>>>(x, xr, n8);
        transpose_pack<<<dim3(QKVC / 32, DMODEL / 32), 256>>>(w_qkv, wq, DMODEL, QKVC);
        transpose_pack<<<dim3(DMODEL / 32, DMODEL / 32), 256>>>(w_proj, wp, DMODEL, DMODEL);
    }

    const int mtiles = (MROWS + BM - 1) / BM;   // 197

    // qkv: A (x) packed, B packed
    gemm_tf32_pk<false, true><<<dim3(QKVC / BN, mtiles), 256, GEMM_SMEM>>>(
        xr, wq, nullptr, qkv, MROWS, QKVC, DMODEL);

    frame_attn_mma<<<Bq * NH * NF * 2, 256, F_SMEM>>>(qkv, attn);
    cls_attn<<<Bq * NH, 256>>>(qkv, attn);

    // proj: A (attn) canonical, B packed
    gemm_tf32_pk<true, false><<<dim3(DMODEL / BN, mtiles), 256, GEMM_SMEM>>>(
        attn, wp, b_proj, out, MROWS, DMODEL, DMODEL);
}

// round 11
// speedup vs baseline: 1.1456x; 1.1456x over previous
#include <cuda_runtime.h>
#include <cstdint>

// ---------------- problem constants ----------------------------------------
#define Bq     16
#define NSEQ   1569            // 1 + 8*196
#define DMODEL 768
#define NH     12
#define DH     64
#define NF     8
#define NPF    196
#define MROWS  (Bq * NSEQ)     // 25104
#define QKVC   (3 * DMODEL)    // 2304

// scratch (no cudaMalloc allowed)
__device__ float g_qkv[(size_t)MROWS * QKVC];     // 231 MB (tf32-rounded by epilogue)
__device__ float g_attn[(size_t)MROWS * DMODEL];  // 77 MB
__device__ float g_x[(size_t)MROWS * DMODEL];     // tf32-rounded x
__device__ float g_wq[(size_t)DMODEL * QKVC];     // rounded w_qkv [K][N]
__device__ float g_wp[(size_t)DMODEL * DMODEL];   // rounded w_proj [K][N]

__device__ __forceinline__ uint32_t f2tf(float x) {
    uint32_t r;
    asm("cvt.rna.tf32.f32 %0, %1;" : "=r"(r) : "f"(x));
    return r;
}
__device__ __forceinline__ float f2tff(float x) { return __uint_as_float(f2tf(x)); }

__device__ __forceinline__ uint32_t s2u(const void* p) {
    return (uint32_t)__cvta_generic_to_shared(p);
}

#define MMA_TF32(c, a0,a1,a2,a3, b0,b1)                                          \
    asm volatile(                                                                 \
        "mma.sync.aligned.m16n8k8.row.col.f32.tf32.tf32.f32 "                     \
        "{%0,%1,%2,%3}, {%4,%5,%6,%7}, {%8,%9}, {%0,%1,%2,%3};"                   \
        : "+f"(c[0]), "+f"(c[1]), "+f"(c[2]), "+f"(c[3])                          \
        : "r"(a0), "r"(a1), "r"(a2), "r"(a3), "r"(b0), "r"(b1))

// ---------------- fused prep: round x, w_qkv, w_proj in one launch ----------
#define N4X ((MROWS * DMODEL) / 4)
#define N4Q ((DMODEL * QKVC) / 4)
#define N4P ((DMODEL * DMODEL) / 4)

__global__ __launch_bounds__(256) void prep_round(
    const float* __restrict__ x,      float* __restrict__ xr,
    const float* __restrict__ w_qkv,  float* __restrict__ wq,
    const float* __restrict__ w_proj, float* __restrict__ wp)
{
    int i = blockIdx.x * 256 + threadIdx.x;
    const float4* src;
    float4* dst;
    if (i < N4X) {
        src = reinterpret_cast<const float4*>(x) + i;
        dst = reinterpret_cast<float4*>(xr) + i;
    } else if (i < N4X + N4Q) {
        src = reinterpret_cast<const float4*>(w_qkv) + (i - N4X);
        dst = reinterpret_cast<float4*>(wq) + (i - N4X);
    } else if (i < N4X + N4Q + N4P) {
        src = reinterpret_cast<const float4*>(w_proj) + (i - N4X - N4Q);
        dst = reinterpret_cast<float4*>(wp) + (i - N4X - N4Q);
    } else {
        return;
    }
    float4 v = *src;
    v.x = f2tff(v.x); v.y = f2tff(v.y); v.z = f2tff(v.z); v.w = f2tff(v.w);
    *dst = v;
}

// ---------------- TF32 GEMM: cp.async 3-stage, 2 CTAs/SM (round-6 exact) ----
#define BM 128
#define BN 128
#define BK 32
#define ASTR 36
#define BSTR 136
#define ABUF (BM * ASTR)
#define BBUF (BK * BSTR)
#define STAGES 3
#define GEMM_SMEM (STAGES * (ABUF + BBUF) * 4)   // 107520 bytes

template <bool BIAS, bool RND>
__global__ __launch_bounds__(256, 2) void gemm_tf32_ca(
    const float* __restrict__ A, const float* __restrict__ Bmat,
    const float* __restrict__ bias, float* __restrict__ C,
    int Mr, int Nc, int Kd)
{
    extern __shared__ float sm[];
    float* As = sm;
    float* Bs = sm + STAGES * ABUF;

    const int tid  = threadIdx.x;
    const int warp = tid >> 5, lane = tid & 31;
    const int gid  = lane >> 2, tig = lane & 3;
    const int wm   = (warp >> 1) * 32;
    const int wn   = (warp & 1) * 64;
    const int brow = blockIdx.y * BM;
    const int bcol = blockIdx.x * BN;

    float acc[2][8][4];
#pragma unroll
    for (int mi = 0; mi < 2; mi++)
#pragma unroll
        for (int ni = 0; ni < 8; ni++)
#pragma unroll
            for (int r = 0; r < 4; r++) acc[mi][ni][r] = 0.f;

    const int nkt = Kd / BK;

    auto issue = [&](int kt) {
        const int buf = kt % STAGES;
        float* Ab = As + buf * ABUF;
        float* Bb = Bs + buf * BBUF;
#pragma unroll
        for (int i = 0; i < 4; i++) {
            int cid = tid + i * 256;
            int row = cid >> 3, c4 = (cid & 7) << 2;
            const float* src = A + (long)(brow + row) * Kd + kt * BK + c4;
            int sz = (brow + row < Mr) ? 16 : 0;
            asm volatile("cp.async.cg.shared.global [%0], [%1], 16, %2;"
                         :: "r"(s2u(Ab + row * ASTR + c4)), "l"(src), "r"(sz));
        }
#pragma unroll
        for (int i = 0; i < 4; i++) {
            int cid = tid + i * 256;
            int kr = cid >> 5, c4 = (cid & 31) << 2;
            const float* src = Bmat + (long)(kt * BK + kr) * Nc + bcol + c4;
            asm volatile("cp.async.cg.shared.global [%0], [%1], 16;"
                         :: "r"(s2u(Bb + kr * BSTR + c4)), "l"(src));
        }
    };

    auto compute = [&](int buf) {
        const uint32_t* Ab = reinterpret_cast<const uint32_t*>(As + buf * ABUF);
        const uint32_t* Bb = reinterpret_cast<const uint32_t*>(Bs + buf * BBUF);
#pragma unroll
        for (int ks = 0; ks < 4; ks++) {
            const int k0 = ks * 8;
            uint32_t af[2][4], bf[8][2];
#pragma unroll
            for (int mi = 0; mi < 2; mi++) {
                const uint32_t* p = Ab + (wm + mi * 16 + gid) * ASTR + k0 + tig;
                af[mi][0] = p[0];
                af[mi][1] = p[8 * ASTR];
                af[mi][2] = p[4];
                af[mi][3] = p[8 * ASTR + 4];
            }
#pragma unroll
            for (int ni = 0; ni < 8; ni++) {
                const uint32_t* p = Bb + (k0 + tig) * BSTR + wn + ni * 8 + gid;
                bf[ni][0] = p[0];
                bf[ni][1] = p[4 * BSTR];
            }
#pragma unroll
            for (int mi = 0; mi < 2; mi++)
#pragma unroll
                for (int ni = 0; ni < 8; ni++)
                    MMA_TF32(acc[mi][ni], af[mi][0], af[mi][1], af[mi][2], af[mi][3],
                             bf[ni][0], bf[ni][1]);
        }
    };

#pragma unroll
    for (int s = 0; s < STAGES - 1; s++) {
        issue(s);
        asm volatile("cp.async.commit_group;");
    }

#pragma unroll 1
    for (int kt = 0; kt < nkt; kt++) {
        asm volatile("cp.async.wait_group %0;" :: "n"(STAGES - 2));
        __syncthreads();
        compute(kt % STAGES);
        if (kt + STAGES - 1 < nkt) issue(kt + STAGES - 1);
        asm volatile("cp.async.commit_group;");
    }

#pragma unroll
    for (int mi = 0; mi < 2; mi++) {
        int r0 = brow + wm + mi * 16 + gid;
#pragma unroll
        for (int ni = 0; ni < 8; ni++) {
            int c0 = bcol + wn + ni * 8 + tig * 2;
            float bx = 0.f, by = 0.f;
            if (BIAS) { bx = bias[c0]; by = bias[c0 + 1]; }
            if (r0 < Mr) {
                float2 v = make_float2(acc[mi][ni][0] + bx, acc[mi][ni][1] + by);
                if (RND) { v.x = f2tff(v.x); v.y = f2tff(v.y); }
                *reinterpret_cast<float2*>(C + (long)r0 * Nc + c0) = v;
            }
            if (r0 + 8 < Mr) {
                float2 v = make_float2(acc[mi][ni][2] + bx, acc[mi][ni][3] + by);
                if (RND) { v.x = f2tff(v.x); v.y = f2tff(v.y); }
                *reinterpret_cast<float2*>(C + (long)(r0 + 8) * Nc + c0) = v;
            }
        }
    }
}

// ---------------- frame attention v3 + fused cls ----------------------------
// Blocks [0, 3072): two blocks per (b,h,frame), shuffle-P flash attention.
// Blocks [3072, 3264): cls attention (1 query over all 1569 keys).
// qkv is already tf32-rounded (GEMM epilogue), so loads are pure copies.
#define KSTR 68
#define VSTR 72
#define F_SMEM ((200 * KSTR + 200 * VSTR) * 4)   // 112640 bytes
#define NFRAMEBLK (Bq * NH * NF * 2)             // 3072

__global__ __launch_bounds__(256, 2) void frame_attn_mma(
    const float* __restrict__ qkv, float* __restrict__ attn)
{
    extern __shared__ float smf[];

    const int tid  = threadIdx.x;
    const int warp = tid >> 5, lane = tid & 31;

    // ================= cls branch (blocks 3072..3263) =================
    if (blockIdx.x >= NFRAMEBLK) {
        const int cbid = blockIdx.x - NFRAMEBLK;   // 0..191
        const int b = cbid / NH;
        const int h = cbid % NH;
        float* qs   = smf;           // [64]
        float* red  = smf + 64;      // [8][64]
        float* redl = smf + 64 + 8 * 64;

        const long rowbase = (long)b * NSEQ;
        const int  hoff    = h * DH;

        if (tid < 64) qs[tid] = qkv[rowbase * QKVC + hoff + tid] * 0.125f;
        __syncthreads();

        float acc[64];
#pragma unroll
        for (int d = 0; d < 64; d++) acc[d] = 0.f;
        float l = 0.f;

        for (int j = tid; j < NSEQ; j += 256) {
            const float* kp = qkv + (rowbase + j) * QKVC + hoff + DMODEL;
            float s0 = 0.f, s1 = 0.f, s2 = 0.f, s3 = 0.f;
#pragma unroll
            for (int d4 = 0; d4 < 16; d4++) {
                float4 kk = *reinterpret_cast<const float4*>(kp + d4 * 4);
                s0 = fmaf(qs[d4 * 4 + 0], kk.x, s0);
                s1 = fmaf(qs[d4 * 4 + 1], kk.y, s1);
                s2 = fmaf(qs[d4 * 4 + 2], kk.z, s2);
                s3 = fmaf(qs[d4 * 4 + 3], kk.w, s3);
            }
            float p = __expf((s0 + s1) + (s2 + s3));
            l += p;
            const float* vp = kp + DMODEL;
#pragma unroll
            for (int d4 = 0; d4 < 16; d4++) {
                float4 vv = *reinterpret_cast<const float4*>(vp + d4 * 4);
                acc[d4 * 4 + 0] = fmaf(p, vv.x, acc[d4 * 4 + 0]);
                acc[d4 * 4 + 1] = fmaf(p, vv.y, acc[d4 * 4 + 1]);
                acc[d4 * 4 + 2] = fmaf(p, vv.z, acc[d4 * 4 + 2]);
                acc[d4 * 4 + 3] = fmaf(p, vv.w, acc[d4 * 4 + 3]);
            }
        }

#pragma unroll
        for (int off = 16; off; off >>= 1) {
            l += __shfl_xor_sync(0xffffffffu, l, off);
#pragma unroll
            for (int d = 0; d < 64; d++)
                acc[d] += __shfl_xor_sync(0xffffffffu, acc[d], off);
        }
        if (lane == 0) {
            redl[warp] = l;
#pragma unroll
            for (int d = 0; d < 64; d++) red[warp * 64 + d] = acc[d];
        }
        __syncthreads();
        if (tid < 64) {
            float s = 0.f, lt = 0.f;
#pragma unroll
            for (int w = 0; w < 8; w++) { s += red[w * 64 + tid]; lt += redl[w]; }
            attn[rowbase * DMODEL + hoff + tid] = f2tff(s / lt);
        }
        return;
    }

    // ================= frame branch (blocks 0..3071) =================
    float* Ks = smf;              // [200][KSTR]; also Q staging scratch
    float* Vs = smf + 200 * KSTR; // [200][VSTR]

    const int gid  = lane >> 2, tig = lane & 3;

    const int bid2 = blockIdx.x;
    const int half = bid2 & 1;
    const int bid  = bid2 >> 1;          // (b*NH + h)*NF + fr
    const int fr   = bid & 7;
    const int h    = (bid >> 3) % NH;
    const int b    = bid / (NF * NH);

    const int tbase  = half * 7;
    const int ntiles = half ? 6 : 7;

    const long rowbase = (long)b * NSEQ;
    const int  hoff    = h * DH;

    const uint32_t* Ku = reinterpret_cast<const uint32_t*>(Ks);
    const uint32_t* Vu = reinterpret_cast<const uint32_t*>(Vs);

    // ---- phase 1: stage this block's Q rows into Ks (qkv pre-rounded) ----
    const int nrows = ntiles * 16;
    for (int idx = tid; idx < nrows * 16; idx += 256) {
        int row = idx >> 4;
        int c4  = (idx & 15) << 2;
        int grow = tbase * 16 + row;
        float4 v = make_float4(0.f, 0.f, 0.f, 0.f);
        if (grow < NPF) {
            const float* qp = qkv + (rowbase + 1 + fr * NPF + grow) * QKVC + hoff + c4;
            float4 u = *reinterpret_cast<const float4*>(qp);
            v.x = u.x * 0.125f;    // power-of-2 scale: exact on tf32 values
            v.y = u.y * 0.125f;
            v.z = u.z * 0.125f;
            v.w = u.w * 0.125f;
        }
        *reinterpret_cast<float4*>(&Ks[row * KSTR + c4]) = v;
    }
    __syncthreads();

    uint32_t af[8][4];
    if (warp < ntiles) {
        const int r0 = warp * 16 + gid;
#pragma unroll
        for (int kc = 0; kc < 8; kc++) {
            int c0 = kc * 8 + tig;
            af[kc][0] = Ku[r0 * KSTR + c0];
            af[kc][1] = Ku[(r0 + 8) * KSTR + c0];
            af[kc][2] = Ku[r0 * KSTR + c0 + 4];
            af[kc][3] = Ku[(r0 + 8) * KSTR + c0 + 4];
        }
    }
    __syncthreads();

    // ---- phase 2: load K/V (197 keys + 3 zero rows), pure copies ----
    for (int idx = tid; idx < 200 * 16; idx += 256) {
        int j  = idx >> 4;
        int c4 = (idx & 15) << 2;
        float4 kk = make_float4(0.f, 0.f, 0.f, 0.f);
        float4 vv = make_float4(0.f, 0.f, 0.f, 0.f);
        if (j < 197) {
            int t = (j == 0) ? 0 : (1 + fr * NPF + j - 1);
            const float* src = qkv + (rowbase + t) * QKVC + hoff;
            kk = *reinterpret_cast<const float4*>(src + DMODEL + c4);
            vv = *reinterpret_cast<const float4*>(src + 2 * DMODEL + c4);
        }
        *reinterpret_cast<float4*>(&Ks[j * KSTR + c4]) = kk;
        *reinterpret_cast<float4*>(&Vs[j * VSTR + c4]) = vv;
    }
    __syncthreads();

    if (warp < ntiles) {
        const int tile = tbase + warp;

        float o[8][4];
#pragma unroll
        for (int dt = 0; dt < 8; dt++)
#pragma unroll
            for (int r = 0; r < 4; r++) o[dt][r] = 0.f;
        float rs0 = 0.f, rs1 = 0.f;

        const int src0 = (lane & ~3) | (tig >> 1);
        const int src1 = src0 + 2;
        const bool oddt = (tig & 1);

#pragma unroll
        for (int chunk = 0; chunk < 5; chunk++) {
            float c[5][4];
#pragma unroll
            for (int ntl = 0; ntl < 5; ntl++)
#pragma unroll
                for (int r = 0; r < 4; r++) c[ntl][r] = 0.f;

#pragma unroll
            for (int ntl = 0; ntl < 5; ntl++) {
                const int nt = chunk * 5 + ntl;
                const uint32_t* kb = Ku + (nt * 8 + gid) * KSTR + tig;
#pragma unroll
                for (int kc = 0; kc < 8; kc++) {
                    uint32_t b0 = kb[kc * 8];
                    uint32_t b1 = kb[kc * 8 + 4];
                    MMA_TF32(c[ntl], af[kc][0], af[kc][1], af[kc][2], af[kc][3],
                             b0, b1);
                }
            }

#pragma unroll
            for (int ntl = 0; ntl < 5; ntl++) {
                const int j0 = (chunk * 5 + ntl) * 8 + tig * 2;
                float p0 = (j0     < 197) ? __expf(c[ntl][0]) : 0.f;
                float p1 = (j0 + 1 < 197) ? __expf(c[ntl][1]) : 0.f;
                float p2 = (j0     < 197) ? __expf(c[ntl][2]) : 0.f;
                float p3 = (j0 + 1 < 197) ? __expf(c[ntl][3]) : 0.f;
                rs0 += p0 + p1;
                rs1 += p2 + p3;
                c[ntl][0] = __uint_as_float(f2tf(p0));
                c[ntl][1] = __uint_as_float(f2tf(p1));
                c[ntl][2] = __uint_as_float(f2tf(p2));
                c[ntl][3] = __uint_as_float(f2tf(p3));
            }

#pragma unroll
            for (int ntl = 0; ntl < 5; ntl++) {
                const int nt = chunk * 5 + ntl;
                float x0 = __shfl_sync(0xffffffffu, c[ntl][0], src0);
                float x1 = __shfl_sync(0xffffffffu, c[ntl][1], src0);
                float x2 = __shfl_sync(0xffffffffu, c[ntl][2], src0);
                float x3 = __shfl_sync(0xffffffffu, c[ntl][3], src0);
                float y0 = __shfl_sync(0xffffffffu, c[ntl][0], src1);
                float y1 = __shfl_sync(0xffffffffu, c[ntl][1], src1);
                float y2 = __shfl_sync(0xffffffffu, c[ntl][2], src1);
                float y3 = __shfl_sync(0xffffffffu, c[ntl][3], src1);
                uint32_t a0 = __float_as_uint(oddt ? x1 : x0);
                uint32_t a1 = __float_as_uint(oddt ? x3 : x2);
                uint32_t a2 = __float_as_uint(oddt ? y1 : y0);
                uint32_t a3 = __float_as_uint(oddt ? y3 : y2);
                const uint32_t* vb = Vu + (nt * 8 + tig) * VSTR + gid;
#pragma unroll
                for (int dt = 0; dt < 8; dt++) {
                    uint32_t b0 = vb[dt * 8];
                    uint32_t b1 = vb[4 * VSTR + dt * 8];
                    MMA_TF32(o[dt], a0, a1, a2, a3, b0, b1);
                }
            }
        }

        rs0 += __shfl_xor_sync(0xffffffffu, rs0, 1);
        rs0 += __shfl_xor_sync(0xffffffffu, rs0, 2);
        rs1 += __shfl_xor_sync(0xffffffffu, rs1, 1);
        rs1 += __shfl_xor_sync(0xffffffffu, rs1, 2);
        const float inv0 = 1.f / rs0;
        const float inv1 = 1.f / rs1;

#pragma unroll
        for (int hh = 0; hh < 2; hh++) {
            int row = tile * 16 + gid + hh * 8;
            if (row < NPF) {
                float inv = hh ? inv1 : inv0;
                float* op = attn + (rowbase + 1 + fr * NPF + row) * DMODEL + hoff;
#pragma unroll
                for (int dt = 0; dt < 8; dt++) {
                    float2 v;
                    v.x = f2tff(o[dt][2 * hh]     * inv);
                    v.y = f2tff(o[dt][2 * hh + 1] * inv);
                    *reinterpret_cast<float2*>(op + dt * 8 + tig * 2) = v;
                }
            }
        }
    }
}

// ---------------- host launch ----------------------------------------------
extern "C" void kernel_launch(void* const* d_in, const int* in_sizes, int n_in,
                              void* d_out, int out_size)
{
    const float* x      = (const float*)d_in[0];
    const float* w_qkv  = (const float*)d_in[1];
    const float* w_proj = (const float*)d_in[2];
    const float* b_proj = (const float*)d_in[3];
    float* out = (float*)d_out;

    float *qkv, *attn, *xr, *wq, *wp;
    cudaGetSymbolAddress((void**)&qkv,  g_qkv);
    cudaGetSymbolAddress((void**)&attn, g_attn);
    cudaGetSymbolAddress((void**)&xr,   g_x);
    cudaGetSymbolAddress((void**)&wq,   g_wq);
    cudaGetSymbolAddress((void**)&wp,   g_wp);

    cudaFuncSetAttribute((const void*)gemm_tf32_ca<false, true>,
                         cudaFuncAttributeMaxDynamicSharedMemorySize, GEMM_SMEM);
    cudaFuncSetAttribute((const void*)gemm_tf32_ca<true, false>,
                         cudaFuncAttributeMaxDynamicSharedMemorySize, GEMM_SMEM);
    cudaFuncSetAttribute(frame_attn_mma,
                         cudaFuncAttributeMaxDynamicSharedMemorySize, F_SMEM);

    // fused prep: round x + both weights (one launch)
    {
        const int total = N4X + N4Q + N4P;
        prep_round<<<(total + 255) / 256, 256>>>(x, xr, w_qkv, wq, w_proj, wp);
    }

    const int mtiles = (MROWS + BM - 1) / BM;   // 197

    // qkv GEMM: epilogue rounds output to tf32 (RND=true)
    gemm_tf32_ca<false, true><<<dim3(QKVC / BN, mtiles), 256, GEMM_SMEM>>>(
        xr, wq, nullptr, qkv, MROWS, QKVC, DMODEL);

    // frame attention + fused cls (3072 + 192 blocks)
    frame_attn_mma<<<NFRAMEBLK + Bq * NH, 256, F_SMEM>>>(qkv, attn);

    // proj GEMM: plain fp32 output + bias
    gemm_tf32_ca<true, false><<<dim3(DMODEL / BN, mtiles), 256, GEMM_SMEM>>>(
        attn, wp, b_proj, out, MROWS, DMODEL, DMODEL);
}

// round 12
// speedup vs baseline: 1.2004x; 1.0479x over previous
#include <cuda_runtime.h>
#include <cstdint>

// ---------------- problem constants ----------------------------------------
#define Bq     16
#define NSEQ   1569            // 1 + 8*196
#define DMODEL 768
#define NH     12
#define DH     64
#define NF     8
#define NPF    196
#define MROWS  (Bq * NSEQ)     // 25104
#define QKVC   (3 * DMODEL)    // 2304

// scratch (no cudaMalloc allowed)
__device__ float g_qkv[(size_t)MROWS * QKVC];     // tf32-rounded by qkv epilogue
__device__ float g_attn[(size_t)MROWS * DMODEL];
__device__ float g_x[(size_t)MROWS * DMODEL];     // tf32-rounded x
__device__ float g_wq[(size_t)DMODEL * QKVC];     // rounded w_qkv [K][N]
__device__ float g_wp[(size_t)DMODEL * DMODEL];   // rounded w_proj [K][N]

__device__ __forceinline__ uint32_t f2tf(float x) {
    uint32_t r;
    asm("cvt.rna.tf32.f32 %0, %1;" : "=r"(r) : "f"(x));
    return r;
}
__device__ __forceinline__ float f2tff(float x) { return __uint_as_float(f2tf(x)); }

__device__ __forceinline__ uint32_t s2u(const void* p) {
    return (uint32_t)__cvta_generic_to_shared(p);
}

#define MMA_TF32(c, a0,a1,a2,a3, b0,b1)                                          \
    asm volatile(                                                                 \
        "mma.sync.aligned.m16n8k8.row.col.f32.tf32.tf32.f32 "                     \
        "{%0,%1,%2,%3}, {%4,%5,%6,%7}, {%8,%9}, {%0,%1,%2,%3};"                   \
        : "+f"(c[0]), "+f"(c[1]), "+f"(c[2]), "+f"(c[3])                          \
        : "r"(a0), "r"(a1), "r"(a2), "r"(a3), "r"(b0), "r"(b1))

// ---------------- fused prep: round x, w_qkv, w_proj in one launch ----------
#define N4X ((MROWS * DMODEL) / 4)
#define N4Q ((DMODEL * QKVC) / 4)
#define N4P ((DMODEL * DMODEL) / 4)

__global__ __launch_bounds__(256) void prep_round(
    const float* __restrict__ x,      float* __restrict__ xr,
    const float* __restrict__ w_qkv,  float* __restrict__ wq,
    const float* __restrict__ w_proj, float* __restrict__ wp)
{
    int i = blockIdx.x * 256 + threadIdx.x;
    const float4* src;
    float4* dst;
    if (i < N4X) {
        src = reinterpret_cast<const float4*>(x) + i;
        dst = reinterpret_cast<float4*>(xr) + i;
    } else if (i < N4X + N4Q) {
        src = reinterpret_cast<const float4*>(w_qkv) + (i - N4X);
        dst = reinterpret_cast<float4*>(wq) + (i - N4X);
    } else if (i < N4X + N4Q + N4P) {
        src = reinterpret_cast<const float4*>(w_proj) + (i - N4X - N4Q);
        dst = reinterpret_cast<float4*>(wp) + (i - N4X - N4Q);
    } else {
        return;
    }
    float4 v = *src;
    v.x = f2tff(v.x); v.y = f2tff(v.y); v.z = f2tff(v.z); v.w = f2tff(v.w);
    *dst = v;
}

// ---------------- TF32 GEMM: cp.async 3-stage, 2 CTAs/SM (round-6 exact) ----
#define BM 128
#define BN 128
#define BK 32
#define ASTR 36
#define BSTR 136
#define ABUF (BM * ASTR)
#define BBUF (BK * BSTR)
#define STAGES 3
#define GEMM_SMEM (STAGES * (ABUF + BBUF) * 4)   // 107520 bytes

template <bool BIAS, bool RND>
__global__ __launch_bounds__(256, 2) void gemm_tf32_ca(
    const float* __restrict__ A, const float* __restrict__ Bmat,
    const float* __restrict__ bias, float* __restrict__ C,
    int Mr, int Nc, int Kd)
{
    extern __shared__ float sm[];
    float* As = sm;
    float* Bs = sm + STAGES * ABUF;

    const int tid  = threadIdx.x;
    const int warp = tid >> 5, lane = tid & 31;
    const int gid  = lane >> 2, tig = lane & 3;
    const int wm   = (warp >> 1) * 32;
    const int wn   = (warp & 1) * 64;
    const int brow = blockIdx.y * BM;
    const int bcol = blockIdx.x * BN;

    float acc[2][8][4];
#pragma unroll
    for (int mi = 0; mi < 2; mi++)
#pragma unroll
        for (int ni = 0; ni < 8; ni++)
#pragma unroll
            for (int r = 0; r < 4; r++) acc[mi][ni][r] = 0.f;

    const int nkt = Kd / BK;

    auto issue = [&](int kt) {
        const int buf = kt % STAGES;
        float* Ab = As + buf * ABUF;
        float* Bb = Bs + buf * BBUF;
#pragma unroll
        for (int i = 0; i < 4; i++) {
            int cid = tid + i * 256;
            int row = cid >> 3, c4 = (cid & 7) << 2;
            const float* src = A + (long)(brow + row) * Kd + kt * BK + c4;
            int sz = (brow + row < Mr) ? 16 : 0;
            asm volatile("cp.async.cg.shared.global [%0], [%1], 16, %2;"
                         :: "r"(s2u(Ab + row * ASTR + c4)), "l"(src), "r"(sz));
        }
#pragma unroll
        for (int i = 0; i < 4; i++) {
            int cid = tid + i * 256;
            int kr = cid >> 5, c4 = (cid & 31) << 2;
            const float* src = Bmat + (long)(kt * BK + kr) * Nc + bcol + c4;
            asm volatile("cp.async.cg.shared.global [%0], [%1], 16;"
                         :: "r"(s2u(Bb + kr * BSTR + c4)), "l"(src));
        }
    };

    auto compute = [&](int buf) {
        const uint32_t* Ab = reinterpret_cast<const uint32_t*>(As + buf * ABUF);
        const uint32_t* Bb = reinterpret_cast<const uint32_t*>(Bs + buf * BBUF);
#pragma unroll
        for (int ks = 0; ks < 4; ks++) {
            const int k0 = ks * 8;
            uint32_t af[2][4], bf[8][2];
#pragma unroll
            for (int mi = 0; mi < 2; mi++) {
                const uint32_t* p = Ab + (wm + mi * 16 + gid) * ASTR + k0 + tig;
                af[mi][0] = p[0];
                af[mi][1] = p[8 * ASTR];
                af[mi][2] = p[4];
                af[mi][3] = p[8 * ASTR + 4];
            }
#pragma unroll
            for (int ni = 0; ni < 8; ni++) {
                const uint32_t* p = Bb + (k0 + tig) * BSTR + wn + ni * 8 + gid;
                bf[ni][0] = p[0];
                bf[ni][1] = p[4 * BSTR];
            }
#pragma unroll
            for (int mi = 0; mi < 2; mi++)
#pragma unroll
                for (int ni = 0; ni < 8; ni++)
                    MMA_TF32(acc[mi][ni], af[mi][0], af[mi][1], af[mi][2], af[mi][3],
                             bf[ni][0], bf[ni][1]);
        }
    };

#pragma unroll
    for (int s = 0; s < STAGES - 1; s++) {
        issue(s);
        asm volatile("cp.async.commit_group;");
    }

#pragma unroll 1
    for (int kt = 0; kt < nkt; kt++) {
        asm volatile("cp.async.wait_group %0;" :: "n"(STAGES - 2));
        __syncthreads();
        compute(kt % STAGES);
        if (kt + STAGES - 1 < nkt) issue(kt + STAGES - 1);
        asm volatile("cp.async.commit_group;");
    }

#pragma unroll
    for (int mi = 0; mi < 2; mi++) {
        int r0 = brow + wm + mi * 16 + gid;
#pragma unroll
        for (int ni = 0; ni < 8; ni++) {
            int c0 = bcol + wn + ni * 8 + tig * 2;
            float bx = 0.f, by = 0.f;
            if (BIAS) { bx = bias[c0]; by = bias[c0 + 1]; }
            if (r0 < Mr) {
                float2 v = make_float2(acc[mi][ni][0] + bx, acc[mi][ni][1] + by);
                if (RND) { v.x = f2tff(v.x); v.y = f2tff(v.y); }
                *reinterpret_cast<float2*>(C + (long)r0 * Nc + c0) = v;
            }
            if (r0 + 8 < Mr) {
                float2 v = make_float2(acc[mi][ni][2] + bx, acc[mi][ni][3] + by);
                if (RND) { v.x = f2tff(v.x); v.y = f2tff(v.y); }
                *reinterpret_cast<float2*>(C + (long)(r0 + 8) * Nc + c0) = v;
            }
        }
    }
}

// ---------------- frame attention v3: shuffle-P, 2 CTAs/SM ------------------
// qkv already tf32-rounded by the GEMM epilogue -> loads are pure copies.
#define KSTR 68
#define VSTR 72
#define F_SMEM ((200 * KSTR + 200 * VSTR) * 4)   // 112640 bytes

__global__ __launch_bounds__(256, 2) void frame_attn_mma(
    const float* __restrict__ qkv, float* __restrict__ attn)
{
    extern __shared__ float smf[];
    float* Ks = smf;              // [200][KSTR]; also Q staging scratch
    float* Vs = smf + 200 * KSTR; // [200][VSTR]

    const int tid  = threadIdx.x;
    const int warp = tid >> 5, lane = tid & 31;
    const int gid  = lane >> 2, tig = lane & 3;

    const int bid2 = blockIdx.x;
    const int half = bid2 & 1;
    const int bid  = bid2 >> 1;          // (b*NH + h)*NF + fr
    const int fr   = bid & 7;
    const int h    = (bid >> 3) % NH;
    const int b    = bid / (NF * NH);

    const int tbase  = half * 7;
    const int ntiles = half ? 6 : 7;

    const long rowbase = (long)b * NSEQ;
    const int  hoff    = h * DH;

    const uint32_t* Ku = reinterpret_cast<const uint32_t*>(Ks);
    const uint32_t* Vu = reinterpret_cast<const uint32_t*>(Vs);

    // ---- phase 1: stage this block's Q rows into Ks (pure copy + exact scale)
    const int nrows = ntiles * 16;
    for (int idx = tid; idx < nrows * 16; idx += 256) {
        int row = idx >> 4;
        int c4  = (idx & 15) << 2;
        int grow = tbase * 16 + row;
        float4 v = make_float4(0.f, 0.f, 0.f, 0.f);
        if (grow < NPF) {
            const float* qp = qkv + (rowbase + 1 + fr * NPF + grow) * QKVC + hoff + c4;
            float4 u = *reinterpret_cast<const float4*>(qp);
            v.x = u.x * 0.125f;   // power-of-2 scale: exact on tf32 values
            v.y = u.y * 0.125f;
            v.z = u.z * 0.125f;
            v.w = u.w * 0.125f;
        }
        *reinterpret_cast<float4*>(&Ks[row * KSTR + c4]) = v;
    }
    __syncthreads();

    uint32_t af[8][4];
    if (warp < ntiles) {
        const int r0 = warp * 16 + gid;
#pragma unroll
        for (int kc = 0; kc < 8; kc++) {
            int c0 = kc * 8 + tig;
            af[kc][0] = Ku[r0 * KSTR + c0];
            af[kc][1] = Ku[(r0 + 8) * KSTR + c0];
            af[kc][2] = Ku[r0 * KSTR + c0 + 4];
            af[kc][3] = Ku[(r0 + 8) * KSTR + c0 + 4];
        }
    }
    __syncthreads();

    // ---- phase 2: load K/V (197 keys + 3 zero rows), pure copies ----
    for (int idx = tid; idx < 200 * 16; idx += 256) {
        int j  = idx >> 4;
        int c4 = (idx & 15) << 2;
        float4 kk = make_float4(0.f, 0.f, 0.f, 0.f);
        float4 vv = make_float4(0.f, 0.f, 0.f, 0.f);
        if (j < 197) {
            int t = (j == 0) ? 0 : (1 + fr * NPF + j - 1);
            const float* src = qkv + (rowbase + t) * QKVC + hoff;
            kk = *reinterpret_cast<const float4*>(src + DMODEL + c4);
            vv = *reinterpret_cast<const float4*>(src + 2 * DMODEL + c4);
        }
        *reinterpret_cast<float4*>(&Ks[j * KSTR + c4]) = kk;
        *reinterpret_cast<float4*>(&Vs[j * VSTR + c4]) = vv;
    }
    __syncthreads();

    if (warp < ntiles) {
        const int tile = tbase + warp;

        float o[8][4];
#pragma unroll
        for (int dt = 0; dt < 8; dt++)
#pragma unroll
            for (int r = 0; r < 4; r++) o[dt][r] = 0.f;
        float rs0 = 0.f, rs1 = 0.f;

        const int src0 = (lane & ~3) | (tig >> 1);
        const int src1 = src0 + 2;
        const bool oddt = (tig & 1);

#pragma unroll
        for (int chunk = 0; chunk < 5; chunk++) {
            float c[5][4];
#pragma unroll
            for (int ntl = 0; ntl < 5; ntl++)
#pragma unroll
                for (int r = 0; r < 4; r++) c[ntl][r] = 0.f;

#pragma unroll
            for (int ntl = 0; ntl < 5; ntl++) {
                const int nt = chunk * 5 + ntl;
                const uint32_t* kb = Ku + (nt * 8 + gid) * KSTR + tig;
#pragma unroll
                for (int kc = 0; kc < 8; kc++) {
                    uint32_t b0 = kb[kc * 8];
                    uint32_t b1 = kb[kc * 8 + 4];
                    MMA_TF32(c[ntl], af[kc][0], af[kc][1], af[kc][2], af[kc][3],
                             b0, b1);
                }
            }

#pragma unroll
            for (int ntl = 0; ntl < 5; ntl++) {
                const int j0 = (chunk * 5 + ntl) * 8 + tig * 2;
                float p0 = (j0     < 197) ? __expf(c[ntl][0]) : 0.f;
                float p1 = (j0 + 1 < 197) ? __expf(c[ntl][1]) : 0.f;
                float p2 = (j0     < 197) ? __expf(c[ntl][2]) : 0.f;
                float p3 = (j0 + 1 < 197) ? __expf(c[ntl][3]) : 0.f;
                rs0 += p0 + p1;
                rs1 += p2 + p3;
                c[ntl][0] = __uint_as_float(f2tf(p0));
                c[ntl][1] = __uint_as_float(f2tf(p1));
                c[ntl][2] = __uint_as_float(f2tf(p2));
                c[ntl][3] = __uint_as_float(f2tf(p3));
            }

#pragma unroll
            for (int ntl = 0; ntl < 5; ntl++) {
                const int nt = chunk * 5 + ntl;
                float x0 = __shfl_sync(0xffffffffu, c[ntl][0], src0);
                float x1 = __shfl_sync(0xffffffffu, c[ntl][1], src0);
                float x2 = __shfl_sync(0xffffffffu, c[ntl][2], src0);
                float x3 = __shfl_sync(0xffffffffu, c[ntl][3], src0);
                float y0 = __shfl_sync(0xffffffffu, c[ntl][0], src1);
                float y1 = __shfl_sync(0xffffffffu, c[ntl][1], src1);
                float y2 = __shfl_sync(0xffffffffu, c[ntl][2], src1);
                float y3 = __shfl_sync(0xffffffffu, c[ntl][3], src1);
                uint32_t a0 = __float_as_uint(oddt ? x1 : x0);
                uint32_t a1 = __float_as_uint(oddt ? x3 : x2);
                uint32_t a2 = __float_as_uint(oddt ? y1 : y0);
                uint32_t a3 = __float_as_uint(oddt ? y3 : y2);
                const uint32_t* vb = Vu + (nt * 8 + tig) * VSTR + gid;
#pragma unroll
                for (int dt = 0; dt < 8; dt++) {
                    uint32_t b0 = vb[dt * 8];
                    uint32_t b1 = vb[4 * VSTR + dt * 8];
                    MMA_TF32(o[dt], a0, a1, a2, a3, b0, b1);
                }
            }
        }

        rs0 += __shfl_xor_sync(0xffffffffu, rs0, 1);
        rs0 += __shfl_xor_sync(0xffffffffu, rs0, 2);
        rs1 += __shfl_xor_sync(0xffffffffu, rs1, 1);
        rs1 += __shfl_xor_sync(0xffffffffu, rs1, 2);
        const float inv0 = 1.f / rs0;
        const float inv1 = 1.f / rs1;

#pragma unroll
        for (int hh = 0; hh < 2; hh++) {
            int row = tile * 16 + gid + hh * 8;
            if (row < NPF) {
                float inv = hh ? inv1 : inv0;
                float* op = attn + (rowbase + 1 + fr * NPF + row) * DMODEL + hoff;
#pragma unroll
                for (int dt = 0; dt < 8; dt++) {
                    float2 v;
                    v.x = f2tff(o[dt][2 * hh]     * inv);
                    v.y = f2tff(o[dt][2 * hh + 1] * inv);
                    *reinterpret_cast<float2*>(op + dt * 8 + tig * 2) = v;
                }
            }
        }
    }
}

// ---------------- cls attention (separate kernel: own register budget) ------
__global__ __launch_bounds__(256) void cls_attn(
    const float* __restrict__ qkv, float* __restrict__ attn)
{
    const int b   = blockIdx.x / NH;
    const int h   = blockIdx.x % NH;
    const int tid = threadIdx.x;

    __shared__ float qs[64];
    __shared__ float red[8][64];
    __shared__ float redl[8];

    const long rowbase = (long)b * NSEQ;
    const int  hoff    = h * DH;

    if (tid < 64) qs[tid] = qkv[rowbase * QKVC + hoff + tid] * 0.125f;
    __syncthreads();

    float acc[64];
#pragma unroll
    for (int d = 0; d < 64; d++) acc[d] = 0.f;
    float l = 0.f;

    for (int j = tid; j < NSEQ; j += 256) {
        const float* kp = qkv + (rowbase + j) * QKVC + hoff + DMODEL;
        float s0 = 0.f, s1 = 0.f, s2 = 0.f, s3 = 0.f;
#pragma unroll
        for (int d4 = 0; d4 < 16; d4++) {
            float4 kk = *reinterpret_cast<const float4*>(kp + d4 * 4);
            s0 = fmaf(qs[d4 * 4 + 0], kk.x, s0);
            s1 = fmaf(qs[d4 * 4 + 1], kk.y, s1);
            s2 = fmaf(qs[d4 * 4 + 2], kk.z, s2);
            s3 = fmaf(qs[d4 * 4 + 3], kk.w, s3);
        }
        float p = __expf((s0 + s1) + (s2 + s3));
        l += p;
        const float* vp = kp + DMODEL;
#pragma unroll
        for (int d4 = 0; d4 < 16; d4++) {
            float4 vv = *reinterpret_cast<const float4*>(vp + d4 * 4);
            acc[d4 * 4 + 0] = fmaf(p, vv.x, acc[d4 * 4 + 0]);
            acc[d4 * 4 + 1] = fmaf(p, vv.y, acc[d4 * 4 + 1]);
            acc[d4 * 4 + 2] = fmaf(p, vv.z, acc[d4 * 4 + 2]);
            acc[d4 * 4 + 3] = fmaf(p, vv.w, acc[d4 * 4 + 3]);
        }
    }

#pragma unroll
    for (int off = 16; off; off >>= 1) {
        l += __shfl_xor_sync(0xffffffffu, l, off);
#pragma unroll
        for (int d = 0; d < 64; d++)
            acc[d] += __shfl_xor_sync(0xffffffffu, acc[d], off);
    }
    const int warp = tid >> 5, lane = tid & 31;
    if (lane == 0) {
        redl[warp] = l;
#pragma unroll
        for (int d = 0; d < 64; d++) red[warp][d] = acc[d];
    }
    __syncthreads();
    if (tid < 64) {
        float s = 0.f, lt = 0.f;
#pragma unroll
        for (int w = 0; w < 8; w++) { s += red[w][tid]; lt += redl[w]; }
        attn[rowbase * DMODEL + hoff + tid] = f2tff(s / lt);
    }
}

// ---------------- host launch ----------------------------------------------
extern "C" void kernel_launch(void* const* d_in, const int* in_sizes, int n_in,
                              void* d_out, int out_size)
{
    const float* x      = (const float*)d_in[0];
    const float* w_qkv  = (const float*)d_in[1];
    const float* w_proj = (const float*)d_in[2];
    const float* b_proj = (const float*)d_in[3];
    float* out = (float*)d_out;

    float *qkv, *attn, *xr, *wq, *wp;
    cudaGetSymbolAddress((void**)&qkv,  g_qkv);
    cudaGetSymbolAddress((void**)&attn, g_attn);
    cudaGetSymbolAddress((void**)&xr,   g_x);
    cudaGetSymbolAddress((void**)&wq,   g_wq);
    cudaGetSymbolAddress((void**)&wp,   g_wp);

    cudaFuncSetAttribute((const void*)gemm_tf32_ca<false, true>,
                         cudaFuncAttributeMaxDynamicSharedMemorySize, GEMM_SMEM);
    cudaFuncSetAttribute((const void*)gemm_tf32_ca<true, false>,
                         cudaFuncAttributeMaxDynamicSharedMemorySize, GEMM_SMEM);
    cudaFuncSetAttribute(frame_attn_mma,
                         cudaFuncAttributeMaxDynamicSharedMemorySize, F_SMEM);

    // fused prep: round x + both weights (one launch)
    {
        const int total = N4X + N4Q + N4P;
        prep_round<<<(total + 255) / 256, 256>>>(x, xr, w_qkv, wq, w_proj, wp);
    }

    const int mtiles = (MROWS + BM - 1) / BM;   // 197

    // qkv GEMM: epilogue rounds output to tf32
    gemm_tf32_ca<false, true><<<dim3(QKVC / BN, mtiles), 256, GEMM_SMEM>>>(
        xr, wq, nullptr, qkv, MROWS, QKVC, DMODEL);

    frame_attn_mma<<<Bq * NH * NF * 2, 256, F_SMEM>>>(qkv, attn);
    cls_attn<<<Bq * NH, 256>>>(qkv, attn);

    // proj GEMM: plain fp32 output + bias
    gemm_tf32_ca<true, false><<<dim3(DMODEL / BN, mtiles), 256, GEMM_SMEM>>>(
        attn, wp, b_proj, out, MROWS, DMODEL, DMODEL);
}

// round 13
// speedup vs baseline: 1.2363x; 1.0298x over previous
#include <cuda_runtime.h>
#include <cstdint>

// ---------------- problem constants ----------------------------------------
#define Bq     16
#define NSEQ   1569            // 1 + 8*196
#define DMODEL 768
#define NH     12
#define DH     64
#define NF     8
#define NPF    196
#define MROWS  (Bq * NSEQ)     // 25104
#define QKVC   (3 * DMODEL)    // 2304

// scratch (no cudaMalloc allowed)
__device__ float g_qkv[(size_t)MROWS * QKVC];     // tf32-rounded by qkv epilogue
__device__ float g_attn[(size_t)MROWS * DMODEL];
__device__ float g_x[(size_t)MROWS * DMODEL];     // tf32-rounded x
__device__ float g_wq[(size_t)DMODEL * QKVC];     // rounded w_qkv [K][N]
__device__ float g_wp[(size_t)DMODEL * DMODEL];   // rounded w_proj [K][N]
__device__ float g_cls[192 * 8 * 65];             // cls split-k partials

__device__ __forceinline__ uint32_t f2tf(float x) {
    uint32_t r;
    asm("cvt.rna.tf32.f32 %0, %1;" : "=r"(r) : "f"(x));
    return r;
}
__device__ __forceinline__ float f2tff(float x) { return __uint_as_float(f2tf(x)); }

__device__ __forceinline__ uint32_t s2u(const void* p) {
    return (uint32_t)__cvta_generic_to_shared(p);
}

#define MMA_TF32(c, a0,a1,a2,a3, b0,b1)                                          \
    asm volatile(                                                                 \
        "mma.sync.aligned.m16n8k8.row.col.f32.tf32.tf32.f32 "                     \
        "{%0,%1,%2,%3}, {%4,%5,%6,%7}, {%8,%9}, {%0,%1,%2,%3};"                   \
        : "+f"(c[0]), "+f"(c[1]), "+f"(c[2]), "+f"(c[3])                          \
        : "r"(a0), "r"(a1), "r"(a2), "r"(a3), "r"(b0), "r"(b1))

// ---------------- fused prep: round x, w_qkv, w_proj in one launch ----------
#define N4X ((MROWS * DMODEL) / 4)
#define N4Q ((DMODEL * QKVC) / 4)
#define N4P ((DMODEL * DMODEL) / 4)

__global__ __launch_bounds__(256) void prep_round(
    const float* __restrict__ x,      float* __restrict__ xr,
    const float* __restrict__ w_qkv,  float* __restrict__ wq,
    const float* __restrict__ w_proj, float* __restrict__ wp)
{
    int i = blockIdx.x * 256 + threadIdx.x;
    const float4* src;
    float4* dst;
    if (i < N4X) {
        src = reinterpret_cast<const float4*>(x) + i;
        dst = reinterpret_cast<float4*>(xr) + i;
    } else if (i < N4X + N4Q) {
        src = reinterpret_cast<const float4*>(w_qkv) + (i - N4X);
        dst = reinterpret_cast<float4*>(wq) + (i - N4X);
    } else if (i < N4X + N4Q + N4P) {
        src = reinterpret_cast<const float4*>(w_proj) + (i - N4X - N4Q);
        dst = reinterpret_cast<float4*>(wp) + (i - N4X - N4Q);
    } else {
        return;
    }
    float4 v = *src;
    v.x = f2tff(v.x); v.y = f2tff(v.y); v.z = f2tff(v.z); v.w = f2tff(v.w);
    *dst = v;
}

// ---------------- TF32 GEMM: cp.async 3-stage, 2 CTAs/SM (round-6 exact) ----
#define BM 128
#define BN 128
#define BK 32
#define ASTR 36
#define BSTR 136
#define ABUF (BM * ASTR)
#define BBUF (BK * BSTR)
#define STAGES 3
#define GEMM_SMEM (STAGES * (ABUF + BBUF) * 4)   // 107520 bytes

template <bool BIAS, bool RND>
__global__ __launch_bounds__(256, 2) void gemm_tf32_ca(
    const float* __restrict__ A, const float* __restrict__ Bmat,
    const float* __restrict__ bias, float* __restrict__ C,
    int Mr, int Nc, int Kd)
{
    extern __shared__ float sm[];
    float* As = sm;
    float* Bs = sm + STAGES * ABUF;

    const int tid  = threadIdx.x;
    const int warp = tid >> 5, lane = tid & 31;
    const int gid  = lane >> 2, tig = lane & 3;
    const int wm   = (warp >> 1) * 32;
    const int wn   = (warp & 1) * 64;
    const int brow = blockIdx.y * BM;
    const int bcol = blockIdx.x * BN;

    float acc[2][8][4];
#pragma unroll
    for (int mi = 0; mi < 2; mi++)
#pragma unroll
        for (int ni = 0; ni < 8; ni++)
#pragma unroll
            for (int r = 0; r < 4; r++) acc[mi][ni][r] = 0.f;

    const int nkt = Kd / BK;

    auto issue = [&](int kt) {
        const int buf = kt % STAGES;
        float* Ab = As + buf * ABUF;
        float* Bb = Bs + buf * BBUF;
#pragma unroll
        for (int i = 0; i < 4; i++) {
            int cid = tid + i * 256;
            int row = cid >> 3, c4 = (cid & 7) << 2;
            const float* src = A + (long)(brow + row) * Kd + kt * BK + c4;
            int sz = (brow + row < Mr) ? 16 : 0;
            asm volatile("cp.async.cg.shared.global [%0], [%1], 16, %2;"
                         :: "r"(s2u(Ab + row * ASTR + c4)), "l"(src), "r"(sz));
        }
#pragma unroll
        for (int i = 0; i < 4; i++) {
            int cid = tid + i * 256;
            int kr = cid >> 5, c4 = (cid & 31) << 2;
            const float* src = Bmat + (long)(kt * BK + kr) * Nc + bcol + c4;
            asm volatile("cp.async.cg.shared.global [%0], [%1], 16;"
                         :: "r"(s2u(Bb + kr * BSTR + c4)), "l"(src));
        }
    };

    auto compute = [&](int buf) {
        const uint32_t* Ab = reinterpret_cast<const uint32_t*>(As + buf * ABUF);
        const uint32_t* Bb = reinterpret_cast<const uint32_t*>(Bs + buf * BBUF);
#pragma unroll
        for (int ks = 0; ks < 4; ks++) {
            const int k0 = ks * 8;
            uint32_t af[2][4], bf[8][2];
#pragma unroll
            for (int mi = 0; mi < 2; mi++) {
                const uint32_t* p = Ab + (wm + mi * 16 + gid) * ASTR + k0 + tig;
                af[mi][0] = p[0];
                af[mi][1] = p[8 * ASTR];
                af[mi][2] = p[4];
                af[mi][3] = p[8 * ASTR + 4];
            }
#pragma unroll
            for (int ni = 0; ni < 8; ni++) {
                const uint32_t* p = Bb + (k0 + tig) * BSTR + wn + ni * 8 + gid;
                bf[ni][0] = p[0];
                bf[ni][1] = p[4 * BSTR];
            }
#pragma unroll
            for (int mi = 0; mi < 2; mi++)
#pragma unroll
                for (int ni = 0; ni < 8; ni++)
                    MMA_TF32(acc[mi][ni], af[mi][0], af[mi][1], af[mi][2], af[mi][3],
                             bf[ni][0], bf[ni][1]);
        }
    };

#pragma unroll
    for (int s = 0; s < STAGES - 1; s++) {
        issue(s);
        asm volatile("cp.async.commit_group;");
    }

#pragma unroll 1
    for (int kt = 0; kt < nkt; kt++) {
        asm volatile("cp.async.wait_group %0;" :: "n"(STAGES - 2));
        __syncthreads();
        compute(kt % STAGES);
        if (kt + STAGES - 1 < nkt) issue(kt + STAGES - 1);
        asm volatile("cp.async.commit_group;");
    }

#pragma unroll
    for (int mi = 0; mi < 2; mi++) {
        int r0 = brow + wm + mi * 16 + gid;
#pragma unroll
        for (int ni = 0; ni < 8; ni++) {
            int c0 = bcol + wn + ni * 8 + tig * 2;
            float bx = 0.f, by = 0.f;
            if (BIAS) { bx = bias[c0]; by = bias[c0 + 1]; }
            if (r0 < Mr) {
                float2 v = make_float2(acc[mi][ni][0] + bx, acc[mi][ni][1] + by);
                if (RND) { v.x = f2tff(v.x); v.y = f2tff(v.y); }
                *reinterpret_cast<float2*>(C + (long)r0 * Nc + c0) = v;
            }
            if (r0 + 8 < Mr) {
                float2 v = make_float2(acc[mi][ni][2] + bx, acc[mi][ni][3] + by);
                if (RND) { v.x = f2tff(v.x); v.y = f2tff(v.y); }
                *reinterpret_cast<float2*>(C + (long)(r0 + 8) * Nc + c0) = v;
            }
        }
    }
}

// ---------------- frame attention v3: shuffle-P, 2 CTAs/SM ------------------
#define KSTR 68
#define VSTR 72
#define F_SMEM ((200 * KSTR + 200 * VSTR) * 4)   // 112640 bytes

__global__ __launch_bounds__(256, 2) void frame_attn_mma(
    const float* __restrict__ qkv, float* __restrict__ attn)
{
    extern __shared__ float smf[];
    float* Ks = smf;              // [200][KSTR]; also Q staging scratch
    float* Vs = smf + 200 * KSTR; // [200][VSTR]

    const int tid  = threadIdx.x;
    const int warp = tid >> 5, lane = tid & 31;
    const int gid  = lane >> 2, tig = lane & 3;

    const int bid2 = blockIdx.x;
    const int half = bid2 & 1;
    const int bid  = bid2 >> 1;          // (b*NH + h)*NF + fr
    const int fr   = bid & 7;
    const int h    = (bid >> 3) % NH;
    const int b    = bid / (NF * NH);

    const int tbase  = half * 7;
    const int ntiles = half ? 6 : 7;

    const long rowbase = (long)b * NSEQ;
    const int  hoff    = h * DH;

    const uint32_t* Ku = reinterpret_cast<const uint32_t*>(Ks);
    const uint32_t* Vu = reinterpret_cast<const uint32_t*>(Vs);

    // ---- phase 1: stage this block's Q rows into Ks (pure copy + exact scale)
    const int nrows = ntiles * 16;
    for (int idx = tid; idx < nrows * 16; idx += 256) {
        int row = idx >> 4;
        int c4  = (idx & 15) << 2;
        int grow = tbase * 16 + row;
        float4 v = make_float4(0.f, 0.f, 0.f, 0.f);
        if (grow < NPF) {
            const float* qp = qkv + (rowbase + 1 + fr * NPF + grow) * QKVC + hoff + c4;
            float4 u = *reinterpret_cast<const float4*>(qp);
            v.x = u.x * 0.125f;   // power-of-2 scale: exact on tf32 values
            v.y = u.y * 0.125f;
            v.z = u.z * 0.125f;
            v.w = u.w * 0.125f;
        }
        *reinterpret_cast<float4*>(&Ks[row * KSTR + c4]) = v;
    }
    __syncthreads();

    uint32_t af[8][4];
    if (warp < ntiles) {
        const int r0 = warp * 16 + gid;
#pragma unroll
        for (int kc = 0; kc < 8; kc++) {
            int c0 = kc * 8 + tig;
            af[kc][0] = Ku[r0 * KSTR + c0];
            af[kc][1] = Ku[(r0 + 8) * KSTR + c0];
            af[kc][2] = Ku[r0 * KSTR + c0 + 4];
            af[kc][3] = Ku[(r0 + 8) * KSTR + c0 + 4];
        }
    }
    __syncthreads();

    // ---- phase 2: load K/V (197 keys + 3 zero rows), pure copies ----
    for (int idx = tid; idx < 200 * 16; idx += 256) {
        int j  = idx >> 4;
        int c4 = (idx & 15) << 2;
        float4 kk = make_float4(0.f, 0.f, 0.f, 0.f);
        float4 vv = make_float4(0.f, 0.f, 0.f, 0.f);
        if (j < 197) {
            int t = (j == 0) ? 0 : (1 + fr * NPF + j - 1);
            const float* src = qkv + (rowbase + t) * QKVC + hoff;
            kk = *reinterpret_cast<const float4*>(src + DMODEL + c4);
            vv = *reinterpret_cast<const float4*>(src + 2 * DMODEL + c4);
        }
        *reinterpret_cast<float4*>(&Ks[j * KSTR + c4]) = kk;
        *reinterpret_cast<float4*>(&Vs[j * VSTR + c4]) = vv;
    }
    __syncthreads();

    if (warp < ntiles) {
        const int tile = tbase + warp;

        float o[8][4];
#pragma unroll
        for (int dt = 0; dt < 8; dt++)
#pragma unroll
            for (int r = 0; r < 4; r++) o[dt][r] = 0.f;
        float rs0 = 0.f, rs1 = 0.f;

        const int src0 = (lane & ~3) | (tig >> 1);
        const int src1 = src0 + 2;
        const bool oddt = (tig & 1);

#pragma unroll
        for (int chunk = 0; chunk < 5; chunk++) {
            float c[5][4];
#pragma unroll
            for (int ntl = 0; ntl < 5; ntl++)
#pragma unroll
                for (int r = 0; r < 4; r++) c[ntl][r] = 0.f;

#pragma unroll
            for (int ntl = 0; ntl < 5; ntl++) {
                const int nt = chunk * 5 + ntl;
                const uint32_t* kb = Ku + (nt * 8 + gid) * KSTR + tig;
#pragma unroll
                for (int kc = 0; kc < 8; kc++) {
                    uint32_t b0 = kb[kc * 8];
                    uint32_t b1 = kb[kc * 8 + 4];
                    MMA_TF32(c[ntl], af[kc][0], af[kc][1], af[kc][2], af[kc][3],
                             b0, b1);
                }
            }

#pragma unroll
            for (int ntl = 0; ntl < 5; ntl++) {
                const int j0 = (chunk * 5 + ntl) * 8 + tig * 2;
                float p0 = (j0     < 197) ? __expf(c[ntl][0]) : 0.f;
                float p1 = (j0 + 1 < 197) ? __expf(c[ntl][1]) : 0.f;
                float p2 = (j0     < 197) ? __expf(c[ntl][2]) : 0.f;
                float p3 = (j0 + 1 < 197) ? __expf(c[ntl][3]) : 0.f;
                rs0 += p0 + p1;
                rs1 += p2 + p3;
                c[ntl][0] = __uint_as_float(f2tf(p0));
                c[ntl][1] = __uint_as_float(f2tf(p1));
                c[ntl][2] = __uint_as_float(f2tf(p2));
                c[ntl][3] = __uint_as_float(f2tf(p3));
            }

#pragma unroll
            for (int ntl = 0; ntl < 5; ntl++) {
                const int nt = chunk * 5 + ntl;
                float x0 = __shfl_sync(0xffffffffu, c[ntl][0], src0);
                float x1 = __shfl_sync(0xffffffffu, c[ntl][1], src0);
                float x2 = __shfl_sync(0xffffffffu, c[ntl][2], src0);
                float x3 = __shfl_sync(0xffffffffu, c[ntl][3], src0);
                float y0 = __shfl_sync(0xffffffffu, c[ntl][0], src1);
                float y1 = __shfl_sync(0xffffffffu, c[ntl][1], src1);
                float y2 = __shfl_sync(0xffffffffu, c[ntl][2], src1);
                float y3 = __shfl_sync(0xffffffffu, c[ntl][3], src1);
                uint32_t a0 = __float_as_uint(oddt ? x1 : x0);
                uint32_t a1 = __float_as_uint(oddt ? x3 : x2);
                uint32_t a2 = __float_as_uint(oddt ? y1 : y0);
                uint32_t a3 = __float_as_uint(oddt ? y3 : y2);
                const uint32_t* vb = Vu + (nt * 8 + tig) * VSTR + gid;
#pragma unroll
                for (int dt = 0; dt < 8; dt++) {
                    uint32_t b0 = vb[dt * 8];
                    uint32_t b1 = vb[4 * VSTR + dt * 8];
                    MMA_TF32(o[dt], a0, a1, a2, a3, b0, b1);
                }
            }
        }

        rs0 += __shfl_xor_sync(0xffffffffu, rs0, 1);
        rs0 += __shfl_xor_sync(0xffffffffu, rs0, 2);
        rs1 += __shfl_xor_sync(0xffffffffu, rs1, 1);
        rs1 += __shfl_xor_sync(0xffffffffu, rs1, 2);
        const float inv0 = 1.f / rs0;
        const float inv1 = 1.f / rs1;

#pragma unroll
        for (int hh = 0; hh < 2; hh++) {
            int row = tile * 16 + gid + hh * 8;
            if (row < NPF) {
                float inv = hh ? inv1 : inv0;
                float* op = attn + (rowbase + 1 + fr * NPF + row) * DMODEL + hoff;
#pragma unroll
                for (int dt = 0; dt < 8; dt++) {
                    float2 v;
                    v.x = f2tff(o[dt][2 * hh]     * inv);
                    v.y = f2tff(o[dt][2 * hh + 1] * inv);
                    *reinterpret_cast<float2*>(op + dt * 8 + tig * 2) = v;
                }
            }
        }
    }
}

// ---------------- cls attention: split-K phase 1 ----------------------------
// Grid 192*8. Block (b,h,chunk) covers <=197 keys. 8 warps; warp w handles
// keys j = j0 + w + 8*i. Lane owns 2 dims. Score via full warp shuffle
// reduce; per-lane acc is 2 floats -> ~40 regs, high occupancy.
#define CLS_CH 197

__global__ __launch_bounds__(256) void cls_p1(
    const float* __restrict__ qkv, float* __restrict__ part)
{
    const int blk  = blockIdx.x;          // (b*NH + h)*8 + c
    const int c    = blk & 7;
    const int bh   = blk >> 3;
    const int b    = bh / NH;
    const int h    = bh % NH;
    const int tid  = threadIdx.x;
    const int warp = tid >> 5, lane = tid & 31;

    __shared__ float qs[64];
    __shared__ float wacc[8][64];
    __shared__ float wl[8];

    const long rowbase = (long)b * NSEQ;
    const int  hoff    = h * DH;

    if (tid < 64) qs[tid] = qkv[rowbase * QKVC + hoff + tid] * 0.125f;
    __syncthreads();

    const int j0 = c * CLS_CH;
    const int jn = (j0 + CLS_CH <= NSEQ) ? CLS_CH : (NSEQ - j0);

    const float q0 = qs[lane * 2];
    const float q1 = qs[lane * 2 + 1];

    float a0 = 0.f, a1 = 0.f, l = 0.f;

    for (int jj = warp; jj < jn; jj += 8) {
        const float* kp = qkv + (rowbase + j0 + jj) * QKVC + hoff + DMODEL;
        float2 kk = *reinterpret_cast<const float2*>(kp + lane * 2);
        float s = q0 * kk.x + q1 * kk.y;
#pragma unroll
        for (int off = 16; off; off >>= 1)
            s += __shfl_xor_sync(0xffffffffu, s, off);
        float p = __expf(s);
        l += p;
        float2 vv = *reinterpret_cast<const float2*>(kp + DMODEL + lane * 2);
        a0 = fmaf(p, vv.x, a0);
        a1 = fmaf(p, vv.y, a1);
    }

    wacc[warp][lane * 2]     = a0;
    wacc[warp][lane * 2 + 1] = a1;
    if (lane == 0) wl[warp] = l;
    __syncthreads();

    if (tid < 64) {
        float s = 0.f;
#pragma unroll
        for (int w = 0; w < 8; w++) s += wacc[w][tid];
        part[(size_t)blk * 65 + tid] = s;
        if (tid == 0) {
            float lt = 0.f;
#pragma unroll
            for (int w = 0; w < 8; w++) lt += wl[w];
            part[(size_t)blk * 65 + 64] = lt;
        }
    }
}

// ---------------- cls attention: split-K phase 2 ----------------------------
__global__ __launch_bounds__(64) void cls_p2(
    const float* __restrict__ part, float* __restrict__ attn)
{
    const int bh = blockIdx.x;            // 0..191
    const int b  = bh / NH;
    const int h  = bh % NH;
    const int d  = threadIdx.x;           // 0..63

    float s = 0.f, lt = 0.f;
#pragma unroll
    for (int c = 0; c < 8; c++) {
        s  += part[(size_t)(bh * 8 + c) * 65 + d];
        lt += part[(size_t)(bh * 8 + c) * 65 + 64];
    }
    attn[(long)b * NSEQ * DMODEL + h * DH + d] = f2tff(s / lt);
}

// ---------------- host launch ----------------------------------------------
extern "C" void kernel_launch(void* const* d_in, const int* in_sizes, int n_in,
                              void* d_out, int out_size)
{
    const float* x      = (const float*)d_in[0];
    const float* w_qkv  = (const float*)d_in[1];
    const float* w_proj = (const float*)d_in[2];
    const float* b_proj = (const float*)d_in[3];
    float* out = (float*)d_out;

    float *qkv, *attn, *xr, *wq, *wp, *clsp;
    cudaGetSymbolAddress((void**)&qkv,  g_qkv);
    cudaGetSymbolAddress((void**)&attn, g_attn);
    cudaGetSymbolAddress((void**)&xr,   g_x);
    cudaGetSymbolAddress((void**)&wq,   g_wq);
    cudaGetSymbolAddress((void**)&wp,   g_wp);
    cudaGetSymbolAddress((void**)&clsp, g_cls);

    cudaFuncSetAttribute((const void*)gemm_tf32_ca<false, true>,
                         cudaFuncAttributeMaxDynamicSharedMemorySize, GEMM_SMEM);
    cudaFuncSetAttribute((const void*)gemm_tf32_ca<true, false>,
                         cudaFuncAttributeMaxDynamicSharedMemorySize, GEMM_SMEM);
    cudaFuncSetAttribute(frame_attn_mma,
                         cudaFuncAttributeMaxDynamicSharedMemorySize, F_SMEM);

    // fused prep: round x + both weights (one launch)
    {
        const int total = N4X + N4Q + N4P;
        prep_round<<<(total + 255) / 256, 256>>>(x, xr, w_qkv, wq, w_proj, wp);
    }

    const int mtiles = (MROWS + BM - 1) / BM;   // 197

    // qkv GEMM: epilogue rounds output to tf32
    gemm_tf32_ca<false, true><<<dim3(QKVC / BN, mtiles), 256, GEMM_SMEM>>>(
        xr, wq, nullptr, qkv, MROWS, QKVC, DMODEL);

    // cls split-K phase 1 (1536 small blocks), then frame attention, then
    // the tiny phase-2 reduce
    cls_p1<<<Bq * NH * 8, 256>>>(qkv, clsp);
    frame_attn_mma<<<Bq * NH * NF * 2, 256, F_SMEM>>>(qkv, attn);
    cls_p2<<<Bq * NH, 64>>>(clsp, attn);

    // proj GEMM: plain fp32 output + bias
    gemm_tf32_ca<true, false><<<dim3(DMODEL / BN, mtiles), 256, GEMM_SMEM>>>(
        attn, wp, b_proj, out, MROWS, DMODEL, DMODEL);
}

// round 14
// speedup vs baseline: 1.3073x; 1.0574x over previous
#include <cuda_runtime.h>
#include <cstdint>

// ---------------- problem constants ----------------------------------------
#define Bq     16
#define NSEQ   1569            // 1 + 8*196
#define DMODEL 768
#define NH     12
#define DH     64
#define NF     8
#define NPF    196
#define MROWS  (Bq * NSEQ)     // 25104
#define QKVC   (3 * DMODEL)    // 2304

// scratch (no cudaMalloc allowed)
__device__ float g_qkv[(size_t)MROWS * QKVC];     // tf32-rounded by qkv epilogue
__device__ float g_attn[(size_t)MROWS * DMODEL];
__device__ float g_x[(size_t)MROWS * DMODEL];     // tf32-rounded x
__device__ float g_wq[(size_t)DMODEL * QKVC];     // rounded w_qkv [K][N]
__device__ float g_wp[(size_t)DMODEL * DMODEL];   // rounded w_proj [K][N]
__device__ float g_cls[192 * 8 * 65];             // cls split-k partials

__device__ __forceinline__ uint32_t f2tf(float x) {
    uint32_t r;
    asm("cvt.rna.tf32.f32 %0, %1;" : "=r"(r) : "f"(x));
    return r;
}
__device__ __forceinline__ float f2tff(float x) { return __uint_as_float(f2tf(x)); }

__device__ __forceinline__ uint32_t s2u(const void* p) {
    return (uint32_t)__cvta_generic_to_shared(p);
}

#define MMA_TF32(c, a0,a1,a2,a3, b0,b1)                                          \
    asm volatile(                                                                 \
        "mma.sync.aligned.m16n8k8.row.col.f32.tf32.tf32.f32 "                     \
        "{%0,%1,%2,%3}, {%4,%5,%6,%7}, {%8,%9}, {%0,%1,%2,%3};"                   \
        : "+f"(c[0]), "+f"(c[1]), "+f"(c[2]), "+f"(c[3])                          \
        : "r"(a0), "r"(a1), "r"(a2), "r"(a3), "r"(b0), "r"(b1))

// ---------------- fused prep: round x, w_qkv, w_proj in one launch ----------
#define N4X ((MROWS * DMODEL) / 4)
#define N4Q ((DMODEL * QKVC) / 4)
#define N4P ((DMODEL * DMODEL) / 4)

__global__ __launch_bounds__(256) void prep_round(
    const float* __restrict__ x,      float* __restrict__ xr,
    const float* __restrict__ w_qkv,  float* __restrict__ wq,
    const float* __restrict__ w_proj, float* __restrict__ wp)
{
    int i = blockIdx.x * 256 + threadIdx.x;
    const float4* src;
    float4* dst;
    if (i < N4X) {
        src = reinterpret_cast<const float4*>(x) + i;
        dst = reinterpret_cast<float4*>(xr) + i;
    } else if (i < N4X + N4Q) {
        src = reinterpret_cast<const float4*>(w_qkv) + (i - N4X);
        dst = reinterpret_cast<float4*>(wq) + (i - N4X);
    } else if (i < N4X + N4Q + N4P) {
        src = reinterpret_cast<const float4*>(w_proj) + (i - N4X - N4Q);
        dst = reinterpret_cast<float4*>(wp) + (i - N4X - N4Q);
    } else {
        return;
    }
    float4 v = *src;
    v.x = f2tff(v.x); v.y = f2tff(v.y); v.z = f2tff(v.z); v.w = f2tff(v.w);
    *dst = v;
}

// ---------------- TF32 GEMM: cp.async 3-stage, 2 CTAs/SM (round-6 exact) ----
#define BM 128
#define BN 128
#define BK 32
#define ASTR 36
#define BSTR 136
#define ABUF (BM * ASTR)
#define BBUF (BK * BSTR)
#define STAGES 3
#define GEMM_SMEM (STAGES * (ABUF + BBUF) * 4)   // 107520 bytes

template <bool BIAS, bool RND>
__global__ __launch_bounds__(256, 2) void gemm_tf32_ca(
    const float* __restrict__ A, const float* __restrict__ Bmat,
    const float* __restrict__ bias, float* __restrict__ C,
    int Mr, int Nc, int Kd)
{
    extern __shared__ float sm[];
    float* As = sm;
    float* Bs = sm + STAGES * ABUF;

    const int tid  = threadIdx.x;
    const int warp = tid >> 5, lane = tid & 31;
    const int gid  = lane >> 2, tig = lane & 3;
    const int wm   = (warp >> 1) * 32;
    const int wn   = (warp & 1) * 64;
    const int brow = blockIdx.y * BM;
    const int bcol = blockIdx.x * BN;

    float acc[2][8][4];
#pragma unroll
    for (int mi = 0; mi < 2; mi++)
#pragma unroll
        for (int ni = 0; ni < 8; ni++)
#pragma unroll
            for (int r = 0; r < 4; r++) acc[mi][ni][r] = 0.f;

    const int nkt = Kd / BK;

    auto issue = [&](int kt) {
        const int buf = kt % STAGES;
        float* Ab = As + buf * ABUF;
        float* Bb = Bs + buf * BBUF;
#pragma unroll
        for (int i = 0; i < 4; i++) {
            int cid = tid + i * 256;
            int row = cid >> 3, c4 = (cid & 7) << 2;
            const float* src = A + (long)(brow + row) * Kd + kt * BK + c4;
            int sz = (brow + row < Mr) ? 16 : 0;
            asm volatile("cp.async.cg.shared.global [%0], [%1], 16, %2;"
                         :: "r"(s2u(Ab + row * ASTR + c4)), "l"(src), "r"(sz));
        }
#pragma unroll
        for (int i = 0; i < 4; i++) {
            int cid = tid + i * 256;
            int kr = cid >> 5, c4 = (cid & 31) << 2;
            const float* src = Bmat + (long)(kt * BK + kr) * Nc + bcol + c4;
            asm volatile("cp.async.cg.shared.global [%0], [%1], 16;"
                         :: "r"(s2u(Bb + kr * BSTR + c4)), "l"(src));
        }
    };

    auto compute = [&](int buf) {
        const uint32_t* Ab = reinterpret_cast<const uint32_t*>(As + buf * ABUF);
        const uint32_t* Bb = reinterpret_cast<const uint32_t*>(Bs + buf * BBUF);
#pragma unroll
        for (int ks = 0; ks < 4; ks++) {
            const int k0 = ks * 8;
            uint32_t af[2][4], bf[8][2];
#pragma unroll
            for (int mi = 0; mi < 2; mi++) {
                const uint32_t* p = Ab + (wm + mi * 16 + gid) * ASTR + k0 + tig;
                af[mi][0] = p[0];
                af[mi][1] = p[8 * ASTR];
                af[mi][2] = p[4];
                af[mi][3] = p[8 * ASTR + 4];
            }
#pragma unroll
            for (int ni = 0; ni < 8; ni++) {
                const uint32_t* p = Bb + (k0 + tig) * BSTR + wn + ni * 8 + gid;
                bf[ni][0] = p[0];
                bf[ni][1] = p[4 * BSTR];
            }
#pragma unroll
            for (int mi = 0; mi < 2; mi++)
#pragma unroll
                for (int ni = 0; ni < 8; ni++)
                    MMA_TF32(acc[mi][ni], af[mi][0], af[mi][1], af[mi][2], af[mi][3],
                             bf[ni][0], bf[ni][1]);
        }
    };

#pragma unroll
    for (int s = 0; s < STAGES - 1; s++) {
        issue(s);
        asm volatile("cp.async.commit_group;");
    }

#pragma unroll 1
    for (int kt = 0; kt < nkt; kt++) {
        asm volatile("cp.async.wait_group %0;" :: "n"(STAGES - 2));
        __syncthreads();
        compute(kt % STAGES);
        if (kt + STAGES - 1 < nkt) issue(kt + STAGES - 1);
        asm volatile("cp.async.commit_group;");
    }

#pragma unroll
    for (int mi = 0; mi < 2; mi++) {
        int r0 = brow + wm + mi * 16 + gid;
#pragma unroll
        for (int ni = 0; ni < 8; ni++) {
            int c0 = bcol + wn + ni * 8 + tig * 2;
            float bx = 0.f, by = 0.f;
            if (BIAS) { bx = bias[c0]; by = bias[c0 + 1]; }
            if (r0 < Mr) {
                float2 v = make_float2(acc[mi][ni][0] + bx, acc[mi][ni][1] + by);
                if (RND) { v.x = f2tff(v.x); v.y = f2tff(v.y); }
                *reinterpret_cast<float2*>(C + (long)r0 * Nc + c0) = v;
            }
            if (r0 + 8 < Mr) {
                float2 v = make_float2(acc[mi][ni][2] + bx, acc[mi][ni][3] + by);
                if (RND) { v.x = f2tff(v.x); v.y = f2tff(v.y); }
                *reinterpret_cast<float2*>(C + (long)(r0 + 8) * Nc + c0) = v;
            }
        }
    }
}

// ---------------- frame attention v4: cp.async K/V overlap ------------------
// V streams into Vs via cp.async while Q is staged in Ks and fragments are
// extracted; K then streams into Ks via cp.async. One wait before compute.
#define KSTR 68
#define VSTR 72
#define F_SMEM ((200 * KSTR + 200 * VSTR) * 4)   // 112640 bytes

__global__ __launch_bounds__(256, 2) void frame_attn_mma(
    const float* __restrict__ qkv, float* __restrict__ attn)
{
    extern __shared__ float smf[];
    float* Ks = smf;              // [200][KSTR]; Q staging, then K
    float* Vs = smf + 200 * KSTR; // [200][VSTR]; V via cp.async from the start

    const int tid  = threadIdx.x;
    const int warp = tid >> 5, lane = tid & 31;
    const int gid  = lane >> 2, tig = lane & 3;

    const int bid2 = blockIdx.x;
    const int half = bid2 & 1;
    const int bid  = bid2 >> 1;          // (b*NH + h)*NF + fr
    const int fr   = bid & 7;
    const int h    = (bid >> 3) % NH;
    const int b    = bid / (NF * NH);

    const int tbase  = half * 7;
    const int ntiles = half ? 6 : 7;

    const long rowbase = (long)b * NSEQ;
    const int  hoff    = h * DH;

    const uint32_t* Ku = reinterpret_cast<const uint32_t*>(Ks);
    const uint32_t* Vu = reinterpret_cast<const uint32_t*>(Vs);

    // ---- phase 0: issue cp.async V -> Vs (rows >=197 zero-filled) ----
    for (int idx = tid; idx < 200 * 16; idx += 256) {
        int j  = idx >> 4;
        int c4 = (idx & 15) << 2;
        int t  = (j == 0) ? 0 : (1 + fr * NPF + j - 1);
        const float* src = (j < 197)
            ? qkv + (rowbase + t) * QKVC + hoff + 2 * DMODEL + c4
            : qkv;                      // dummy (sz=0 -> zero-fill)
        int sz = (j < 197) ? 16 : 0;
        asm volatile("cp.async.cg.shared.global [%0], [%1], 16, %2;"
                     :: "r"(s2u(Vs + j * VSTR + c4)), "l"(src), "r"(sz));
    }
    asm volatile("cp.async.commit_group;");

    // ---- phase 1: stage Q rows into Ks (pure copy + exact /8 scale) ----
    const int nrows = ntiles * 16;
    for (int idx = tid; idx < nrows * 16; idx += 256) {
        int row = idx >> 4;
        int c4  = (idx & 15) << 2;
        int grow = tbase * 16 + row;
        float4 v = make_float4(0.f, 0.f, 0.f, 0.f);
        if (grow < NPF) {
            const float* qp = qkv + (rowbase + 1 + fr * NPF + grow) * QKVC + hoff + c4;
            float4 u = *reinterpret_cast<const float4*>(qp);
            v.x = u.x * 0.125f;
            v.y = u.y * 0.125f;
            v.z = u.z * 0.125f;
            v.w = u.w * 0.125f;
        }
        *reinterpret_cast<float4*>(&Ks[row * KSTR + c4]) = v;
    }
    __syncthreads();

    uint32_t af[8][4];
    if (warp < ntiles) {
        const int r0 = warp * 16 + gid;
#pragma unroll
        for (int kc = 0; kc < 8; kc++) {
            int c0 = kc * 8 + tig;
            af[kc][0] = Ku[r0 * KSTR + c0];
            af[kc][1] = Ku[(r0 + 8) * KSTR + c0];
            af[kc][2] = Ku[r0 * KSTR + c0 + 4];
            af[kc][3] = Ku[(r0 + 8) * KSTR + c0 + 4];
        }
    }
    __syncthreads();

    // ---- phase 2: cp.async K -> Ks (overwrites Q stage; fragments in regs) --
    for (int idx = tid; idx < 200 * 16; idx += 256) {
        int j  = idx >> 4;
        int c4 = (idx & 15) << 2;
        int t  = (j == 0) ? 0 : (1 + fr * NPF + j - 1);
        const float* src = (j < 197)
            ? qkv + (rowbase + t) * QKVC + hoff + DMODEL + c4
            : qkv;
        int sz = (j < 197) ? 16 : 0;
        asm volatile("cp.async.cg.shared.global [%0], [%1], 16, %2;"
                     :: "r"(s2u(Ks + j * KSTR + c4)), "l"(src), "r"(sz));
    }
    asm volatile("cp.async.commit_group;");
    asm volatile("cp.async.wait_group 0;");
    __syncthreads();

    if (warp < ntiles) {
        const int tile = tbase + warp;

        float o[8][4];
#pragma unroll
        for (int dt = 0; dt < 8; dt++)
#pragma unroll
            for (int r = 0; r < 4; r++) o[dt][r] = 0.f;
        float rs0 = 0.f, rs1 = 0.f;

        const int src0 = (lane & ~3) | (tig >> 1);
        const int src1 = src0 + 2;
        const bool oddt = (tig & 1);

#pragma unroll
        for (int chunk = 0; chunk < 5; chunk++) {
            float c[5][4];
#pragma unroll
            for (int ntl = 0; ntl < 5; ntl++)
#pragma unroll
                for (int r = 0; r < 4; r++) c[ntl][r] = 0.f;

#pragma unroll
            for (int ntl = 0; ntl < 5; ntl++) {
                const int nt = chunk * 5 + ntl;
                const uint32_t* kb = Ku + (nt * 8 + gid) * KSTR + tig;
#pragma unroll
                for (int kc = 0; kc < 8; kc++) {
                    uint32_t b0 = kb[kc * 8];
                    uint32_t b1 = kb[kc * 8 + 4];
                    MMA_TF32(c[ntl], af[kc][0], af[kc][1], af[kc][2], af[kc][3],
                             b0, b1);
                }
            }

#pragma unroll
            for (int ntl = 0; ntl < 5; ntl++) {
                const int j0 = (chunk * 5 + ntl) * 8 + tig * 2;
                float p0 = (j0     < 197) ? __expf(c[ntl][0]) : 0.f;
                float p1 = (j0 + 1 < 197) ? __expf(c[ntl][1]) : 0.f;
                float p2 = (j0     < 197) ? __expf(c[ntl][2]) : 0.f;
                float p3 = (j0 + 1 < 197) ? __expf(c[ntl][3]) : 0.f;
                rs0 += p0 + p1;
                rs1 += p2 + p3;
                c[ntl][0] = __uint_as_float(f2tf(p0));
                c[ntl][1] = __uint_as_float(f2tf(p1));
                c[ntl][2] = __uint_as_float(f2tf(p2));
                c[ntl][3] = __uint_as_float(f2tf(p3));
            }

#pragma unroll
            for (int ntl = 0; ntl < 5; ntl++) {
                const int nt = chunk * 5 + ntl;
                float x0 = __shfl_sync(0xffffffffu, c[ntl][0], src0);
                float x1 = __shfl_sync(0xffffffffu, c[ntl][1], src0);
                float x2 = __shfl_sync(0xffffffffu, c[ntl][2], src0);
                float x3 = __shfl_sync(0xffffffffu, c[ntl][3], src0);
                float y0 = __shfl_sync(0xffffffffu, c[ntl][0], src1);
                float y1 = __shfl_sync(0xffffffffu, c[ntl][1], src1);
                float y2 = __shfl_sync(0xffffffffu, c[ntl][2], src1);
                float y3 = __shfl_sync(0xffffffffu, c[ntl][3], src1);
                uint32_t a0 = __float_as_uint(oddt ? x1 : x0);
                uint32_t a1 = __float_as_uint(oddt ? x3 : x2);
                uint32_t a2 = __float_as_uint(oddt ? y1 : y0);
                uint32_t a3 = __float_as_uint(oddt ? y3 : y2);
                const uint32_t* vb = Vu + (nt * 8 + tig) * VSTR + gid;
#pragma unroll
                for (int dt = 0; dt < 8; dt++) {
                    uint32_t b0 = vb[dt * 8];
                    uint32_t b1 = vb[4 * VSTR + dt * 8];
                    MMA_TF32(o[dt], a0, a1, a2, a3, b0, b1);
                }
            }
        }

        rs0 += __shfl_xor_sync(0xffffffffu, rs0, 1);
        rs0 += __shfl_xor_sync(0xffffffffu, rs0, 2);
        rs1 += __shfl_xor_sync(0xffffffffu, rs1, 1);
        rs1 += __shfl_xor_sync(0xffffffffu, rs1, 2);
        const float inv0 = 1.f / rs0;
        const float inv1 = 1.f / rs1;

#pragma unroll
        for (int hh = 0; hh < 2; hh++) {
            int row = tile * 16 + gid + hh * 8;
            if (row < NPF) {
                float inv = hh ? inv1 : inv0;
                float* op = attn + (rowbase + 1 + fr * NPF + row) * DMODEL + hoff;
#pragma unroll
                for (int dt = 0; dt < 8; dt++) {
                    float2 v;
                    v.x = f2tff(o[dt][2 * hh]     * inv);
                    v.y = f2tff(o[dt][2 * hh + 1] * inv);
                    *reinterpret_cast<float2*>(op + dt * 8 + tig * 2) = v;
                }
            }
        }
    }
}

// ---------------- cls attention: split-K phase 1 ----------------------------
#define CLS_CH 197

__global__ __launch_bounds__(256) void cls_p1(
    const float* __restrict__ qkv, float* __restrict__ part)
{
    const int blk  = blockIdx.x;          // (b*NH + h)*8 + c
    const int c    = blk & 7;
    const int bh   = blk >> 3;
    const int b    = bh / NH;
    const int h    = bh % NH;
    const int tid  = threadIdx.x;
    const int warp = tid >> 5, lane = tid & 31;

    __shared__ float qs[64];
    __shared__ float wacc[8][64];
    __shared__ float wl[8];

    const long rowbase = (long)b * NSEQ;
    const int  hoff    = h * DH;

    if (tid < 64) qs[tid] = qkv[rowbase * QKVC + hoff + tid] * 0.125f;
    __syncthreads();

    const int j0 = c * CLS_CH;
    const int jn = (j0 + CLS_CH <= NSEQ) ? CLS_CH : (NSEQ - j0);

    const float q0 = qs[lane * 2];
    const float q1 = qs[lane * 2 + 1];

    float a0 = 0.f, a1 = 0.f, l = 0.f;

    for (int jj = warp; jj < jn; jj += 8) {
        const float* kp = qkv + (rowbase + j0 + jj) * QKVC + hoff + DMODEL;
        float2 kk = *reinterpret_cast<const float2*>(kp + lane * 2);
        float s = q0 * kk.x + q1 * kk.y;
#pragma unroll
        for (int off = 16; off; off >>= 1)
            s += __shfl_xor_sync(0xffffffffu, s, off);
        float p = __expf(s);
        l += p;
        float2 vv = *reinterpret_cast<const float2*>(kp + DMODEL + lane * 2);
        a0 = fmaf(p, vv.x, a0);
        a1 = fmaf(p, vv.y, a1);
    }

    wacc[warp][lane * 2]     = a0;
    wacc[warp][lane * 2 + 1] = a1;
    if (lane == 0) wl[warp] = l;
    __syncthreads();

    if (tid < 64) {
        float s = 0.f;
#pragma unroll
        for (int w = 0; w < 8; w++) s += wacc[w][tid];
        part[(size_t)blk * 65 + tid] = s;
        if (tid == 0) {
            float lt = 0.f;
#pragma unroll
            for (int w = 0; w < 8; w++) lt += wl[w];
            part[(size_t)blk * 65 + 64] = lt;
        }
    }
}

// ---------------- cls attention: split-K phase 2 ----------------------------
__global__ __launch_bounds__(64) void cls_p2(
    const float* __restrict__ part, float* __restrict__ attn)
{
    const int bh = blockIdx.x;            // 0..191
    const int b  = bh / NH;
    const int h  = bh % NH;
    const int d  = threadIdx.x;           // 0..63

    float s = 0.f, lt = 0.f;
#pragma unroll
    for (int c = 0; c < 8; c++) {
        s  += part[(size_t)(bh * 8 + c) * 65 + d];
        lt += part[(size_t)(bh * 8 + c) * 65 + 64];
    }
    attn[(long)b * NSEQ * DMODEL + h * DH + d] = f2tff(s / lt);
}

// ---------------- host launch ----------------------------------------------
extern "C" void kernel_launch(void* const* d_in, const int* in_sizes, int n_in,
                              void* d_out, int out_size)
{
    const float* x      = (const float*)d_in[0];
    const float* w_qkv  = (const float*)d_in[1];
    const float* w_proj = (const float*)d_in[2];
    const float* b_proj = (const float*)d_in[3];
    float* out = (float*)d_out;

    float *qkv, *attn, *xr, *wq, *wp, *clsp;
    cudaGetSymbolAddress((void**)&qkv,  g_qkv);
    cudaGetSymbolAddress((void**)&attn, g_attn);
    cudaGetSymbolAddress((void**)&xr,   g_x);
    cudaGetSymbolAddress((void**)&wq,   g_wq);
    cudaGetSymbolAddress((void**)&wp,   g_wp);
    cudaGetSymbolAddress((void**)&clsp, g_cls);

    cudaFuncSetAttribute((const void*)gemm_tf32_ca<false, true>,
                         cudaFuncAttributeMaxDynamicSharedMemorySize, GEMM_SMEM);
    cudaFuncSetAttribute((const void*)gemm_tf32_ca<true, false>,
                         cudaFuncAttributeMaxDynamicSharedMemorySize, GEMM_SMEM);
    cudaFuncSetAttribute(frame_attn_mma,
                         cudaFuncAttributeMaxDynamicSharedMemorySize, F_SMEM);

    // fused prep: round x + both weights (one launch)
    {
        const int total = N4X + N4Q + N4P;
        prep_round<<<(total + 255) / 256, 256>>>(x, xr, w_qkv, wq, w_proj, wp);
    }

    const int mtiles = (MROWS + BM - 1) / BM;   // 197

    // qkv GEMM: epilogue rounds output to tf32
    gemm_tf32_ca<false, true><<<dim3(QKVC / BN, mtiles), 256, GEMM_SMEM>>>(
        xr, wq, nullptr, qkv, MROWS, QKVC, DMODEL);

    cls_p1<<<Bq * NH * 8, 256>>>(qkv, clsp);
    frame_attn_mma<<<Bq * NH * NF * 2, 256, F_SMEM>>>(qkv, attn);
    cls_p2<<<Bq * NH, 64>>>(clsp, attn);

    // proj GEMM: plain fp32 output + bias
    gemm_tf32_ca<true, false><<<dim3(DMODEL / BN, mtiles), 256, GEMM_SMEM>>>(
        attn, wp, b_proj, out, MROWS, DMODEL, DMODEL);
}

// round 15
// speedup vs baseline: 1.9022x; 1.4551x over previous
#include <cuda_runtime.h>
#include <cuda_fp16.h>
#include <cstdint>

// ---------------- problem constants ----------------------------------------
#define Bq     16
#define NSEQ   1569            // 1 + 8*196
#define DMODEL 768
#define NH     12
#define DH     64
#define NF     8
#define NPF    196
#define MROWS  (Bq * NSEQ)     // 25104
#define QKVC   (3 * DMODEL)    // 2304

// scratch (no cudaMalloc allowed)
__device__ float  g_qkv[(size_t)MROWS * QKVC];      // fp32, tf32-rounded
__device__ __half g_attnh[(size_t)MROWS * DMODEL];  // attention out, fp16
__device__ __half g_xh[(size_t)MROWS * DMODEL];     // x, fp16
__device__ __half g_wqh[(size_t)QKVC * DMODEL];     // w_qkv^T [N][K] fp16
__device__ __half g_wph[(size_t)DMODEL * DMODEL];   // w_proj^T [N][K] fp16
__device__ float  g_cls[192 * 8 * 65];              // cls split-k partials

__device__ __forceinline__ uint32_t f2tf(float x) {
    uint32_t r;
    asm("cvt.rna.tf32.f32 %0, %1;" : "=r"(r) : "f"(x));
    return r;
}
__device__ __forceinline__ float f2tff(float x) { return __uint_as_float(f2tf(x)); }

__device__ __forceinline__ uint32_t s2u(const void* p) {
    return (uint32_t)__cvta_generic_to_shared(p);
}

#define MMA_TF32(c, a0,a1,a2,a3, b0,b1)                                          \
    asm volatile(                                                                 \
        "mma.sync.aligned.m16n8k8.row.col.f32.tf32.tf32.f32 "                     \
        "{%0,%1,%2,%3}, {%4,%5,%6,%7}, {%8,%9}, {%0,%1,%2,%3};"                   \
        : "+f"(c[0]), "+f"(c[1]), "+f"(c[2]), "+f"(c[3])                          \
        : "r"(a0), "r"(a1), "r"(a2), "r"(a3), "r"(b0), "r"(b1))

#define MMA_F16(c, a0,a1,a2,a3, b0,b1)                                           \
    asm volatile(                                                                 \
        "mma.sync.aligned.m16n8k16.row.col.f32.f16.f16.f32 "                      \
        "{%0,%1,%2,%3}, {%4,%5,%6,%7}, {%8,%9}, {%0,%1,%2,%3};"                   \
        : "+f"(c[0]), "+f"(c[1]), "+f"(c[2]), "+f"(c[3])                          \
        : "r"(a0), "r"(a1), "r"(a2), "r"(a3), "r"(b0), "r"(b1))

// ---------------- prep: x fp32 -> fp16 --------------------------------------
#define N4X ((MROWS * DMODEL) / 4)

__global__ __launch_bounds__(256) void prep_x(
    const float* __restrict__ in, __half* __restrict__ out)
{
    int i = blockIdx.x * 256 + threadIdx.x;
    if (i < N4X) {
        float4 v = reinterpret_cast<const float4*>(in)[i];
        __half2* op = reinterpret_cast<__half2*>(out) + i * 2;
        op[0] = __floats2half2_rn(v.x, v.y);
        op[1] = __floats2half2_rn(v.z, v.w);
    }
}

// ---------------- prep: transpose fp32 [R][C] -> fp16 [C][R] ----------------
__global__ __launch_bounds__(256) void transpose_h(
    const float* __restrict__ in, __half* __restrict__ out, int R, int C)
{
    __shared__ float t[32][33];
    const int bx = blockIdx.x * 32;   // C offset
    const int by = blockIdx.y * 32;   // R offset
    const int tx = threadIdx.x & 31, ty = threadIdx.x >> 5;  // 32 x 8
#pragma unroll
    for (int j = 0; j < 4; j++)
        t[ty + j * 8][tx] = in[(long)(by + ty + j * 8) * C + bx + tx];
    __syncthreads();
#pragma unroll
    for (int j = 0; j < 4; j++)
        out[(long)(bx + ty + j * 8) * R + by + tx] = __float2half(t[tx][ty + j * 8]);
}

// ---------------- FP16 GEMM: cp.async 3-stage, 2 CTAs/SM --------------------
// A [M][K] fp16 k-major, Bt [N][K] fp16 k-major. Chunk = 64 halves of K.
// Smem tiles [128][36] u32 (= 72 halves/row incl. pad); fragment word index
// = 4*gid + tig (mod 32): conflict-free, same proven pattern as tf32 kernel.
#define BM 128
#define BN 128
#define HSTR 36                 // u32 per row
#define HBUF (128 * HSTR)       // u32 per tile
#define STAGES 3
#define GEMM_SMEM (STAGES * 2 * HBUF * 4)   // 110592 bytes

template <bool BIAS, bool RND>
__global__ __launch_bounds__(256, 2) void gemm_f16(
    const __half* __restrict__ A, const __half* __restrict__ Bt,
    const float* __restrict__ bias, float* __restrict__ C,
    int Mr, int Nc, int Kd)
{
    extern __shared__ uint32_t smu[];
    uint32_t* As = smu;
    uint32_t* Bs = smu + STAGES * HBUF;

    const int tid  = threadIdx.x;
    const int warp = tid >> 5, lane = tid & 31;
    const int gid  = lane >> 2, tig = lane & 3;
    const int wm   = (warp >> 1) * 32;    // 4 warps along M
    const int wn   = (warp & 1) * 64;     // 2 warps along N
    const int brow = blockIdx.y * BM;
    const int bcol = blockIdx.x * BN;

    float acc[2][8][4];
#pragma unroll
    for (int mi = 0; mi < 2; mi++)
#pragma unroll
        for (int ni = 0; ni < 8; ni++)
#pragma unroll
            for (int r = 0; r < 4; r++) acc[mi][ni][r] = 0.f;

    const int nkt = Kd / 64;    // 64 halves of K per chunk

    auto issue = [&](int kt) {
        const int buf = kt % STAGES;
        uint32_t* Ab = As + buf * HBUF;
        uint32_t* Bb = Bs + buf * HBUF;
#pragma unroll
        for (int i = 0; i < 4; i++) {
            int cid = tid + i * 256;
            int row = cid >> 3, c16 = cid & 7;
            const __half* src = A + (long)(brow + row) * Kd + kt * 64 + c16 * 8;
            int sz = (brow + row < Mr) ? 16 : 0;
            asm volatile("cp.async.cg.shared.global [%0], [%1], 16, %2;"
                         :: "r"(s2u(Ab + row * HSTR + c16 * 4)), "l"(src), "r"(sz));
        }
#pragma unroll
        for (int i = 0; i < 4; i++) {
            int cid = tid + i * 256;
            int row = cid >> 3, c16 = cid & 7;
            const __half* src = Bt + (long)(bcol + row) * Kd + kt * 64 + c16 * 8;
            asm volatile("cp.async.cg.shared.global [%0], [%1], 16;"
                         :: "r"(s2u(Bb + row * HSTR + c16 * 4)), "l"(src));
        }
    };

    auto compute = [&](int buf) {
        const uint32_t* Ab = As + buf * HBUF;
        const uint32_t* Bb = Bs + buf * HBUF;
#pragma unroll
        for (int ks = 0; ks < 4; ks++) {
            const int k0 = ks * 8;          // u32 offset (= 16 halves of K)
            uint32_t af[2][4], bf[8][2];
#pragma unroll
            for (int mi = 0; mi < 2; mi++) {
                const uint32_t* p = Ab + (wm + mi * 16 + gid) * HSTR + k0 + tig;
                af[mi][0] = p[0];
                af[mi][1] = p[8 * HSTR];
                af[mi][2] = p[4];
                af[mi][3] = p[8 * HSTR + 4];
            }
#pragma unroll
            for (int ni = 0; ni < 8; ni++) {
                const uint32_t* p = Bb + (wn + ni * 8 + gid) * HSTR + k0 + tig;
                bf[ni][0] = p[0];
                bf[ni][1] = p[4];
            }
#pragma unroll
            for (int mi = 0; mi < 2; mi++)
#pragma unroll
                for (int ni = 0; ni < 8; ni++)
                    MMA_F16(acc[mi][ni], af[mi][0], af[mi][1], af[mi][2], af[mi][3],
                            bf[ni][0], bf[ni][1]);
        }
    };

#pragma unroll
    for (int s = 0; s < STAGES - 1; s++) {
        issue(s);
        asm volatile("cp.async.commit_group;");
    }

#pragma unroll 1
    for (int kt = 0; kt < nkt; kt++) {
        asm volatile("cp.async.wait_group %0;" :: "n"(STAGES - 2));
        __syncthreads();
        compute(kt % STAGES);
        if (kt + STAGES - 1 < nkt) issue(kt + STAGES - 1);
        asm volatile("cp.async.commit_group;");
    }

#pragma unroll
    for (int mi = 0; mi < 2; mi++) {
        int r0 = brow + wm + mi * 16 + gid;
#pragma unroll
        for (int ni = 0; ni < 8; ni++) {
            int c0 = bcol + wn + ni * 8 + tig * 2;
            float bx = 0.f, by = 0.f;
            if (BIAS) { bx = bias[c0]; by = bias[c0 + 1]; }
            if (r0 < Mr) {
                float2 v = make_float2(acc[mi][ni][0] + bx, acc[mi][ni][1] + by);
                if (RND) { v.x = f2tff(v.x); v.y = f2tff(v.y); }
                *reinterpret_cast<float2*>(C + (long)r0 * Nc + c0) = v;
            }
            if (r0 + 8 < Mr) {
                float2 v = make_float2(acc[mi][ni][2] + bx, acc[mi][ni][3] + by);
                if (RND) { v.x = f2tff(v.x); v.y = f2tff(v.y); }
                *reinterpret_cast<float2*>(C + (long)(r0 + 8) * Nc + c0) = v;
            }
        }
    }
}

// ---------------- frame attention v4: cp.async K/V overlap ------------------
#define KSTR 68
#define VSTR 72
#define F_SMEM ((200 * KSTR + 200 * VSTR) * 4)   // 112640 bytes

__global__ __launch_bounds__(256, 2) void frame_attn_mma(
    const float* __restrict__ qkv, __half* __restrict__ attn)
{
    extern __shared__ float smf[];
    float* Ks = smf;              // [200][KSTR]; Q staging, then K
    float* Vs = smf + 200 * KSTR; // [200][VSTR]; V via cp.async from the start

    const int tid  = threadIdx.x;
    const int warp = tid >> 5, lane = tid & 31;
    const int gid  = lane >> 2, tig = lane & 3;

    const int bid2 = blockIdx.x;
    const int half = bid2 & 1;
    const int bid  = bid2 >> 1;          // (b*NH + h)*NF + fr
    const int fr   = bid & 7;
    const int h    = (bid >> 3) % NH;
    const int b    = bid / (NF * NH);

    const int tbase  = half * 7;
    const int ntiles = half ? 6 : 7;

    const long rowbase = (long)b * NSEQ;
    const int  hoff    = h * DH;

    const uint32_t* Ku = reinterpret_cast<const uint32_t*>(Ks);
    const uint32_t* Vu = reinterpret_cast<const uint32_t*>(Vs);

    // ---- phase 0: issue cp.async V -> Vs (rows >=197 zero-filled) ----
    for (int idx = tid; idx < 200 * 16; idx += 256) {
        int j  = idx >> 4;
        int c4 = (idx & 15) << 2;
        int t  = (j == 0) ? 0 : (1 + fr * NPF + j - 1);
        const float* src = (j < 197)
            ? qkv + (rowbase + t) * QKVC + hoff + 2 * DMODEL + c4
            : qkv;
        int sz = (j < 197) ? 16 : 0;
        asm volatile("cp.async.cg.shared.global [%0], [%1], 16, %2;"
                     :: "r"(s2u(Vs + j * VSTR + c4)), "l"(src), "r"(sz));
    }
    asm volatile("cp.async.commit_group;");

    // ---- phase 1: stage Q rows into Ks (pure copy + exact /8 scale) ----
    const int nrows = ntiles * 16;
    for (int idx = tid; idx < nrows * 16; idx += 256) {
        int row = idx >> 4;
        int c4  = (idx & 15) << 2;
        int grow = tbase * 16 + row;
        float4 v = make_float4(0.f, 0.f, 0.f, 0.f);
        if (grow < NPF) {
            const float* qp = qkv + (rowbase + 1 + fr * NPF + grow) * QKVC + hoff + c4;
            float4 u = *reinterpret_cast<const float4*>(qp);
            v.x = u.x * 0.125f;
            v.y = u.y * 0.125f;
            v.z = u.z * 0.125f;
            v.w = u.w * 0.125f;
        }
        *reinterpret_cast<float4*>(&Ks[row * KSTR + c4]) = v;
    }
    __syncthreads();

    uint32_t af[8][4];
    if (warp < ntiles) {
        const int r0 = warp * 16 + gid;
#pragma unroll
        for (int kc = 0; kc < 8; kc++) {
            int c0 = kc * 8 + tig;
            af[kc][0] = Ku[r0 * KSTR + c0];
            af[kc][1] = Ku[(r0 + 8) * KSTR + c0];
            af[kc][2] = Ku[r0 * KSTR + c0 + 4];
            af[kc][3] = Ku[(r0 + 8) * KSTR + c0 + 4];
        }
    }
    __syncthreads();

    // ---- phase 2: cp.async K -> Ks (overwrites Q stage) ----
    for (int idx = tid; idx < 200 * 16; idx += 256) {
        int j  = idx >> 4;
        int c4 = (idx & 15) << 2;
        int t  = (j == 0) ? 0 : (1 + fr * NPF + j - 1);
        const float* src = (j < 197)
            ? qkv + (rowbase + t) * QKVC + hoff + DMODEL + c4
            : qkv;
        int sz = (j < 197) ? 16 : 0;
        asm volatile("cp.async.cg.shared.global [%0], [%1], 16, %2;"
                     :: "r"(s2u(Ks + j * KSTR + c4)), "l"(src), "r"(sz));
    }
    asm volatile("cp.async.commit_group;");
    asm volatile("cp.async.wait_group 0;");
    __syncthreads();

    if (warp < ntiles) {
        const int tile = tbase + warp;

        float o[8][4];
#pragma unroll
        for (int dt = 0; dt < 8; dt++)
#pragma unroll
            for (int r = 0; r < 4; r++) o[dt][r] = 0.f;
        float rs0 = 0.f, rs1 = 0.f;

        const int src0 = (lane & ~3) | (tig >> 1);
        const int src1 = src0 + 2;
        const bool oddt = (tig & 1);

#pragma unroll
        for (int chunk = 0; chunk < 5; chunk++) {
            float c[5][4];
#pragma unroll
            for (int ntl = 0; ntl < 5; ntl++)
#pragma unroll
                for (int r = 0; r < 4; r++) c[ntl][r] = 0.f;

#pragma unroll
            for (int ntl = 0; ntl < 5; ntl++) {
                const int nt = chunk * 5 + ntl;
                const uint32_t* kb = Ku + (nt * 8 + gid) * KSTR + tig;
#pragma unroll
                for (int kc = 0; kc < 8; kc++) {
                    uint32_t b0 = kb[kc * 8];
                    uint32_t b1 = kb[kc * 8 + 4];
                    MMA_TF32(c[ntl], af[kc][0], af[kc][1], af[kc][2], af[kc][3],
                             b0, b1);
                }
            }

#pragma unroll
            for (int ntl = 0; ntl < 5; ntl++) {
                const int j0 = (chunk * 5 + ntl) * 8 + tig * 2;
                float p0 = (j0     < 197) ? __expf(c[ntl][0]) : 0.f;
                float p1 = (j0 + 1 < 197) ? __expf(c[ntl][1]) : 0.f;
                float p2 = (j0     < 197) ? __expf(c[ntl][2]) : 0.f;
                float p3 = (j0 + 1 < 197) ? __expf(c[ntl][3]) : 0.f;
                rs0 += p0 + p1;
                rs1 += p2 + p3;
                c[ntl][0] = __uint_as_float(f2tf(p0));
                c[ntl][1] = __uint_as_float(f2tf(p1));
                c[ntl][2] = __uint_as_float(f2tf(p2));
                c[ntl][3] = __uint_as_float(f2tf(p3));
            }

#pragma unroll
            for (int ntl = 0; ntl < 5; ntl++) {
                const int nt = chunk * 5 + ntl;
                float x0 = __shfl_sync(0xffffffffu, c[ntl][0], src0);
                float x1 = __shfl_sync(0xffffffffu, c[ntl][1], src0);
                float x2 = __shfl_sync(0xffffffffu, c[ntl][2], src0);
                float x3 = __shfl_sync(0xffffffffu, c[ntl][3], src0);
                float y0 = __shfl_sync(0xffffffffu, c[ntl][0], src1);
                float y1 = __shfl_sync(0xffffffffu, c[ntl][1], src1);
                float y2 = __shfl_sync(0xffffffffu, c[ntl][2], src1);
                float y3 = __shfl_sync(0xffffffffu, c[ntl][3], src1);
                uint32_t a0 = __float_as_uint(oddt ? x1 : x0);
                uint32_t a1 = __float_as_uint(oddt ? x3 : x2);
                uint32_t a2 = __float_as_uint(oddt ? y1 : y0);
                uint32_t a3 = __float_as_uint(oddt ? y3 : y2);
                const uint32_t* vb = Vu + (nt * 8 + tig) * VSTR + gid;
#pragma unroll
                for (int dt = 0; dt < 8; dt++) {
                    uint32_t b0 = vb[dt * 8];
                    uint32_t b1 = vb[4 * VSTR + dt * 8];
                    MMA_TF32(o[dt], a0, a1, a2, a3, b0, b1);
                }
            }
        }

        rs0 += __shfl_xor_sync(0xffffffffu, rs0, 1);
        rs0 += __shfl_xor_sync(0xffffffffu, rs0, 2);
        rs1 += __shfl_xor_sync(0xffffffffu, rs1, 1);
        rs1 += __shfl_xor_sync(0xffffffffu, rs1, 2);
        const float inv0 = 1.f / rs0;
        const float inv1 = 1.f / rs1;

#pragma unroll
        for (int hh = 0; hh < 2; hh++) {
            int row = tile * 16 + gid + hh * 8;
            if (row < NPF) {
                float inv = hh ? inv1 : inv0;
                __half2* op = reinterpret_cast<__half2*>(
                    attn + (rowbase + 1 + fr * NPF + row) * DMODEL + hoff);
#pragma unroll
                for (int dt = 0; dt < 8; dt++)
                    op[dt * 4 + tig] = __floats2half2_rn(
                        o[dt][2 * hh] * inv, o[dt][2 * hh + 1] * inv);
            }
        }
    }
}

// ---------------- cls attention: split-K phase 1 ----------------------------
#define CLS_CH 197

__global__ __launch_bounds__(256) void cls_p1(
    const float* __restrict__ qkv, float* __restrict__ part)
{
    const int blk  = blockIdx.x;          // (b*NH + h)*8 + c
    const int c    = blk & 7;
    const int bh   = blk >> 3;
    const int b    = bh / NH;
    const int h    = bh % NH;
    const int tid  = threadIdx.x;
    const int warp = tid >> 5, lane = tid & 31;

    __shared__ float qs[64];
    __shared__ float wacc[8][64];
    __shared__ float wl[8];

    const long rowbase = (long)b * NSEQ;
    const int  hoff    = h * DH;

    if (tid < 64) qs[tid] = qkv[rowbase * QKVC + hoff + tid] * 0.125f;
    __syncthreads();

    const int j0 = c * CLS_CH;
    const int jn = (j0 + CLS_CH <= NSEQ) ? CLS_CH : (NSEQ - j0);

    const float q0 = qs[lane * 2];
    const float q1 = qs[lane * 2 + 1];

    float a0 = 0.f, a1 = 0.f, l = 0.f;

    for (int jj = warp; jj < jn; jj += 8) {
        const float* kp = qkv + (rowbase + j0 + jj) * QKVC + hoff + DMODEL;
        float2 kk = *reinterpret_cast<const float2*>(kp + lane * 2);
        float s = q0 * kk.x + q1 * kk.y;
#pragma unroll
        for (int off = 16; off; off >>= 1)
            s += __shfl_xor_sync(0xffffffffu, s, off);
        float p = __expf(s);
        l += p;
        float2 vv = *reinterpret_cast<const float2*>(kp + DMODEL + lane * 2);
        a0 = fmaf(p, vv.x, a0);
        a1 = fmaf(p, vv.y, a1);
    }

    wacc[warp][lane * 2]     = a0;
    wacc[warp][lane * 2 + 1] = a1;
    if (lane == 0) wl[warp] = l;
    __syncthreads();

    if (tid < 64) {
        float s = 0.f;
#pragma unroll
        for (int w = 0; w < 8; w++) s += wacc[w][tid];
        part[(size_t)blk * 65 + tid] = s;
        if (tid == 0) {
            float lt = 0.f;
#pragma unroll
            for (int w = 0; w < 8; w++) lt += wl[w];
            part[(size_t)blk * 65 + 64] = lt;
        }
    }
}

// ---------------- cls attention: split-K phase 2 ----------------------------
__global__ __launch_bounds__(64) void cls_p2(
    const float* __restrict__ part, __half* __restrict__ attn)
{
    const int bh = blockIdx.x;            // 0..191
    const int b  = bh / NH;
    const int h  = bh % NH;
    const int d  = threadIdx.x;           // 0..63

    float s = 0.f, lt = 0.f;
#pragma unroll
    for (int c = 0; c < 8; c++) {
        s  += part[(size_t)(bh * 8 + c) * 65 + d];
        lt += part[(size_t)(bh * 8 + c) * 65 + 64];
    }
    attn[(long)b * NSEQ * DMODEL + h * DH + d] = __float2half(s / lt);
}

// ---------------- host launch ----------------------------------------------
extern "C" void kernel_launch(void* const* d_in, const int* in_sizes, int n_in,
                              void* d_out, int out_size)
{
    const float* x      = (const float*)d_in[0];
    const float* w_qkv  = (const float*)d_in[1];
    const float* w_proj = (const float*)d_in[2];
    const float* b_proj = (const float*)d_in[3];
    float* out = (float*)d_out;

    float *qkv, *clsp;
    __half *attnh, *xh, *wqh, *wph;
    cudaGetSymbolAddress((void**)&qkv,   g_qkv);
    cudaGetSymbolAddress((void**)&attnh, g_attnh);
    cudaGetSymbolAddress((void**)&xh,    g_xh);
    cudaGetSymbolAddress((void**)&wqh,   g_wqh);
    cudaGetSymbolAddress((void**)&wph,   g_wph);
    cudaGetSymbolAddress((void**)&clsp,  g_cls);

    cudaFuncSetAttribute((const void*)gemm_f16<false, true>,
                         cudaFuncAttributeMaxDynamicSharedMemorySize, GEMM_SMEM);
    cudaFuncSetAttribute((const void*)gemm_f16<true, false>,
                         cudaFuncAttributeMaxDynamicSharedMemorySize, GEMM_SMEM);
    cudaFuncSetAttribute(frame_attn_mma,
                         cudaFuncAttributeMaxDynamicSharedMemorySize, F_SMEM);

    // prep: x -> fp16; weights -> transposed fp16 [N][K]
    prep_x<<<(N4X + 255) / 256, 256>>>(x, xh);
    transpose_h<<<dim3(QKVC / 32, DMODEL / 32), 256>>>(w_qkv, wqh, DMODEL, QKVC);
    transpose_h<<<dim3(DMODEL / 32, DMODEL / 32), 256>>>(w_proj, wph, DMODEL, DMODEL);

    const int mtiles = (MROWS + BM - 1) / BM;   // 197

    // qkv GEMM (fp16 inputs, fp32 out rounded to tf32 for attention)
    gemm_f16<false, true><<<dim3(QKVC / BN, mtiles), 256, GEMM_SMEM>>>(
        xh, wqh, nullptr, qkv, MROWS, QKVC, DMODEL);

    cls_p1<<<Bq * NH * 8, 256>>>(qkv, clsp);
    frame_attn_mma<<<Bq * NH * NF * 2, 256, F_SMEM>>>(qkv, attnh);
    cls_p2<<<Bq * NH, 64>>>(clsp, attnh);

    // proj GEMM (fp16 attn + fp16 weights, fp32 out + bias)
    gemm_f16<true, false><<<dim3(DMODEL / BN, mtiles), 256, GEMM_SMEM>>>(
        attnh, wph, b_proj, out, MROWS, DMODEL, DMODEL);
}

// round 16
// speedup vs baseline: 2.0336x; 1.0690x over previous
#include <cuda_runtime.h>
#include <cuda_fp16.h>
#include <cstdint>

// ---------------- problem constants ----------------------------------------
#define Bq     16
#define NSEQ   1569            // 1 + 8*196
#define DMODEL 768
#define NH     12
#define DH     64
#define NF     8
#define NPF    196
#define MROWS  (Bq * NSEQ)     // 25104
#define QKVC   (3 * DMODEL)    // 2304
#define QKH_W  (2 * DMODEL)    // 1536 (Q|K fp16 buffer width)

// scratch (no cudaMalloc allowed)
__device__ __half g_qkh[(size_t)MROWS * QKH_W];     // Q|K fp16 (qkv epilogue)
__device__ float  g_v[(size_t)MROWS * DMODEL];      // V fp32, tf32-rounded
__device__ __half g_attnh[(size_t)MROWS * DMODEL];  // attention out, fp16
__device__ __half g_xh[(size_t)MROWS * DMODEL];     // x, fp16
__device__ __half g_wqh[(size_t)QKVC * DMODEL];     // w_qkv^T [N][K] fp16
__device__ __half g_wph[(size_t)DMODEL * DMODEL];   // w_proj^T [N][K] fp16
__device__ float  g_cls[192 * 8 * 65];              // cls split-k partials

__device__ __forceinline__ uint32_t f2tf(float x) {
    uint32_t r;
    asm("cvt.rna.tf32.f32 %0, %1;" : "=r"(r) : "f"(x));
    return r;
}
__device__ __forceinline__ float f2tff(float x) { return __uint_as_float(f2tf(x)); }

__device__ __forceinline__ uint32_t s2u(const void* p) {
    return (uint32_t)__cvta_generic_to_shared(p);
}

#define MMA_TF32(c, a0,a1,a2,a3, b0,b1)                                          \
    asm volatile(                                                                 \
        "mma.sync.aligned.m16n8k8.row.col.f32.tf32.tf32.f32 "                     \
        "{%0,%1,%2,%3}, {%4,%5,%6,%7}, {%8,%9}, {%0,%1,%2,%3};"                   \
        : "+f"(c[0]), "+f"(c[1]), "+f"(c[2]), "+f"(c[3])                          \
        : "r"(a0), "r"(a1), "r"(a2), "r"(a3), "r"(b0), "r"(b1))

#define MMA_F16(c, a0,a1,a2,a3, b0,b1)                                           \
    asm volatile(                                                                 \
        "mma.sync.aligned.m16n8k16.row.col.f32.f16.f16.f32 "                      \
        "{%0,%1,%2,%3}, {%4,%5,%6,%7}, {%8,%9}, {%0,%1,%2,%3};"                   \
        : "+f"(c[0]), "+f"(c[1]), "+f"(c[2]), "+f"(c[3])                          \
        : "r"(a0), "r"(a1), "r"(a2), "r"(a3), "r"(b0), "r"(b1))

// ---------------- prep: x fp32 -> fp16 --------------------------------------
#define N4X ((MROWS * DMODEL) / 4)

__global__ __launch_bounds__(256) void prep_x(
    const float* __restrict__ in, __half* __restrict__ out)
{
    int i = blockIdx.x * 256 + threadIdx.x;
    if (i < N4X) {
        float4 v = reinterpret_cast<const float4*>(in)[i];
        __half2* op = reinterpret_cast<__half2*>(out) + i * 2;
        op[0] = __floats2half2_rn(v.x, v.y);
        op[1] = __floats2half2_rn(v.z, v.w);
    }
}

// ---------------- prep: transpose fp32 [R][C] -> fp16 [C][R] ----------------
__global__ __launch_bounds__(256) void transpose_h(
    const float* __restrict__ in, __half* __restrict__ out, int R, int C)
{
    __shared__ float t[32][33];
    const int bx = blockIdx.x * 32;
    const int by = blockIdx.y * 32;
    const int tx = threadIdx.x & 31, ty = threadIdx.x >> 5;
#pragma unroll
    for (int j = 0; j < 4; j++)
        t[ty + j * 8][tx] = in[(long)(by + ty + j * 8) * C + bx + tx];
    __syncthreads();
#pragma unroll
    for (int j = 0; j < 4; j++)
        out[(long)(bx + ty + j * 8) * R + by + tx] = __float2half(t[tx][ty + j * 8]);
}

// ---------------- FP16 GEMM: cp.async 3-stage, 2 CTAs/SM --------------------
// OUTM=0: proj (fp32 C + bias). OUTM=1: qkv split (Q,K fp16 -> qkh; V fp32
// tf32-rounded -> vout). The 1536 column boundary is a multiple of BN, so
// the split branch is block-uniform.
#define BM 128
#define BN 128
#define HSTR 36
#define HBUF (128 * HSTR)
#define STAGES 3
#define GEMM_SMEM (STAGES * 2 * HBUF * 4)   // 110592 bytes

template <int OUTM>
__global__ __launch_bounds__(256, 2) void gemm_f16(
    const __half* __restrict__ A, const __half* __restrict__ Bt,
    const float* __restrict__ bias, float* __restrict__ Cf,
    __half* __restrict__ qkh, float* __restrict__ vout,
    int Mr, int Nc, int Kd)
{
    extern __shared__ uint32_t smu[];
    uint32_t* As = smu;
    uint32_t* Bs = smu + STAGES * HBUF;

    const int tid  = threadIdx.x;
    const int warp = tid >> 5, lane = tid & 31;
    const int gid  = lane >> 2, tig = lane & 3;
    const int wm   = (warp >> 1) * 32;
    const int wn   = (warp & 1) * 64;
    const int brow = blockIdx.y * BM;
    const int bcol = blockIdx.x * BN;

    float acc[2][8][4];
#pragma unroll
    for (int mi = 0; mi < 2; mi++)
#pragma unroll
        for (int ni = 0; ni < 8; ni++)
#pragma unroll
            for (int r = 0; r < 4; r++) acc[mi][ni][r] = 0.f;

    const int nkt = Kd / 64;

    auto issue = [&](int kt) {
        const int buf = kt % STAGES;
        uint32_t* Ab = As + buf * HBUF;
        uint32_t* Bb = Bs + buf * HBUF;
#pragma unroll
        for (int i = 0; i < 4; i++) {
            int cid = tid + i * 256;
            int row = cid >> 3, c16 = cid & 7;
            const __half* src = A + (long)(brow + row) * Kd + kt * 64 + c16 * 8;
            int sz = (brow + row < Mr) ? 16 : 0;
            asm volatile("cp.async.cg.shared.global [%0], [%1], 16, %2;"
                         :: "r"(s2u(Ab + row * HSTR + c16 * 4)), "l"(src), "r"(sz));
        }
#pragma unroll
        for (int i = 0; i < 4; i++) {
            int cid = tid + i * 256;
            int row = cid >> 3, c16 = cid & 7;
            const __half* src = Bt + (long)(bcol + row) * Kd + kt * 64 + c16 * 8;
            asm volatile("cp.async.cg.shared.global [%0], [%1], 16;"
                         :: "r"(s2u(Bb + row * HSTR + c16 * 4)), "l"(src));
        }
    };

    auto compute = [&](int buf) {
        const uint32_t* Ab = As + buf * HBUF;
        const uint32_t* Bb = Bs + buf * HBUF;
#pragma unroll
        for (int ks = 0; ks < 4; ks++) {
            const int k0 = ks * 8;
            uint32_t af[2][4], bf[8][2];
#pragma unroll
            for (int mi = 0; mi < 2; mi++) {
                const uint32_t* p = Ab + (wm + mi * 16 + gid) * HSTR + k0 + tig;
                af[mi][0] = p[0];
                af[mi][1] = p[8 * HSTR];
                af[mi][2] = p[4];
                af[mi][3] = p[8 * HSTR + 4];
            }
#pragma unroll
            for (int ni = 0; ni < 8; ni++) {
                const uint32_t* p = Bb + (wn + ni * 8 + gid) * HSTR + k0 + tig;
                bf[ni][0] = p[0];
                bf[ni][1] = p[4];
            }
#pragma unroll
            for (int mi = 0; mi < 2; mi++)
#pragma unroll
                for (int ni = 0; ni < 8; ni++)
                    MMA_F16(acc[mi][ni], af[mi][0], af[mi][1], af[mi][2], af[mi][3],
                            bf[ni][0], bf[ni][1]);
        }
    };

#pragma unroll
    for (int s = 0; s < STAGES - 1; s++) {
        issue(s);
        asm volatile("cp.async.commit_group;");
    }

#pragma unroll 1
    for (int kt = 0; kt < nkt; kt++) {
        asm volatile("cp.async.wait_group %0;" :: "n"(STAGES - 2));
        __syncthreads();
        compute(kt % STAGES);
        if (kt + STAGES - 1 < nkt) issue(kt + STAGES - 1);
        asm volatile("cp.async.commit_group;");
    }

    const bool toV = (OUTM == 1) && (bcol >= QKH_W);   // block-uniform
#pragma unroll
    for (int mi = 0; mi < 2; mi++) {
        int r0 = brow + wm + mi * 16 + gid;
#pragma unroll
        for (int ni = 0; ni < 8; ni++) {
            int c0 = bcol + wn + ni * 8 + tig * 2;
#pragma unroll
            for (int hh = 0; hh < 2; hh++) {
                int rr = r0 + hh * 8;
                if (rr >= Mr) continue;
                float v0 = acc[mi][ni][2 * hh];
                float v1 = acc[mi][ni][2 * hh + 1];
                if (OUTM == 0) {
                    v0 += bias[c0]; v1 += bias[c0 + 1];
                    *reinterpret_cast<float2*>(Cf + (long)rr * Nc + c0) =
                        make_float2(v0, v1);
                } else if (toV) {
                    *reinterpret_cast<float2*>(vout + (long)rr * DMODEL + c0 - QKH_W) =
                        make_float2(f2tff(v0), f2tff(v1));
                } else {
                    *reinterpret_cast<__half2*>(qkh + (long)rr * QKH_W + c0) =
                        __floats2half2_rn(v0, v1);
                }
            }
        }
    }
}

// ---------------- frame attention v5: fp16 S-phase, tf32 O-phase ------------
// K fp16 [200 rows][36 u32] (row = key, 64 halves of dim + pad); V fp32
// [200][72]. Q staged fp16 into the K region first. cp.async overlap as v4.
#define KSTRU 36                // u32 per K row
#define VSTR  72                // floats per V row
#define F_SMEM ((200 * KSTRU + 200 * VSTR) * 4)   // 86400 bytes

__global__ __launch_bounds__(256, 2) void frame_attn_mma(
    const __half* __restrict__ qkh, const float* __restrict__ vsrc,
    __half* __restrict__ attn)
{
    extern __shared__ uint32_t smu[];
    uint32_t* Kh = smu;                       // Q staging, then K (fp16 words)
    float*    Vs = reinterpret_cast<float*>(smu + 200 * KSTRU);

    const int tid  = threadIdx.x;
    const int warp = tid >> 5, lane = tid & 31;
    const int gid  = lane >> 2, tig = lane & 3;

    const int bid2 = blockIdx.x;
    const int half = bid2 & 1;
    const int bid  = bid2 >> 1;          // (b*NH + h)*NF + fr
    const int fr   = bid & 7;
    const int h    = (bid >> 3) % NH;
    const int b    = bid / (NF * NH);

    const int tbase  = half * 7;
    const int ntiles = half ? 6 : 7;

    const long rowbase = (long)b * NSEQ;
    const int  hoff    = h * DH;

    const uint32_t* Vu = reinterpret_cast<const uint32_t*>(Vs);

    // ---- phase 0: cp.async V (fp32) -> Vs ----
    for (int idx = tid; idx < 200 * 16; idx += 256) {
        int j  = idx >> 4;
        int c4 = (idx & 15) << 2;
        int t  = (j == 0) ? 0 : (1 + fr * NPF + j - 1);
        const float* src = (j < 197)
            ? vsrc + (rowbase + t) * DMODEL + hoff + c4
            : vsrc;
        int sz = (j < 197) ? 16 : 0;
        asm volatile("cp.async.cg.shared.global [%0], [%1], 16, %2;"
                     :: "r"(s2u(Vs + j * VSTR + c4)), "l"(src), "r"(sz));
    }
    asm volatile("cp.async.commit_group;");

    // ---- phase 1: stage Q (fp16) into Kh region, scale by 1/8 (exact) ----
    const int nrows = ntiles * 16;
    const __half2 hs = __float2half2_rn(0.125f);
    for (int idx = tid; idx < nrows * 8; idx += 256) {
        int row = idx >> 3;
        int c8  = idx & 7;              // 8-half chunk
        int grow = tbase * 16 + row;
        uint4 v = make_uint4(0u, 0u, 0u, 0u);
        if (grow < NPF) {
            const uint4* qp = reinterpret_cast<const uint4*>(
                qkh + (rowbase + 1 + fr * NPF + grow) * QKH_W + hoff) + c8;
            uint4 u = *qp;
            __half2 h0 = __hmul2(*reinterpret_cast<__half2*>(&u.x), hs);
            __half2 h1 = __hmul2(*reinterpret_cast<__half2*>(&u.y), hs);
            __half2 h2 = __hmul2(*reinterpret_cast<__half2*>(&u.z), hs);
            __half2 h3 = __hmul2(*reinterpret_cast<__half2*>(&u.w), hs);
            v.x = *reinterpret_cast<uint32_t*>(&h0);
            v.y = *reinterpret_cast<uint32_t*>(&h1);
            v.z = *reinterpret_cast<uint32_t*>(&h2);
            v.w = *reinterpret_cast<uint32_t*>(&h3);
        }
        *reinterpret_cast<uint4*>(Kh + row * KSTRU + c8 * 4) = v;
    }
    __syncthreads();

    // ---- Q fragments (fp16 m16n8k16 A): af[kc][4], kc = 4 k16 chunks ----
    uint32_t af[4][4];
    if (warp < ntiles) {
        const int r0 = warp * 16 + gid;
#pragma unroll
        for (int kc = 0; kc < 4; kc++) {
            int c0 = kc * 8 + tig;
            af[kc][0] = Kh[r0 * KSTRU + c0];
            af[kc][1] = Kh[(r0 + 8) * KSTRU + c0];
            af[kc][2] = Kh[r0 * KSTRU + c0 + 4];
            af[kc][3] = Kh[(r0 + 8) * KSTRU + c0 + 4];
        }
    }
    __syncthreads();

    // ---- phase 2: cp.async K (fp16) -> Kh ----
    for (int idx = tid; idx < 200 * 8; idx += 256) {
        int j   = idx >> 3;
        int c16 = idx & 7;              // 8-half (16B) chunk
        int t   = (j == 0) ? 0 : (1 + fr * NPF + j - 1);
        const __half* src = (j < 197)
            ? qkh + (rowbase + t) * QKH_W + DMODEL + hoff + c16 * 8
            : qkh;
        int sz = (j < 197) ? 16 : 0;
        asm volatile("cp.async.cg.shared.global [%0], [%1], 16, %2;"
                     :: "r"(s2u(Kh + j * KSTRU + c16 * 4)), "l"(src), "r"(sz));
    }
    asm volatile("cp.async.commit_group;");
    asm volatile("cp.async.wait_group 0;");
    __syncthreads();

    if (warp < ntiles) {
        const int tile = tbase + warp;

        float o[8][4];
#pragma unroll
        for (int dt = 0; dt < 8; dt++)
#pragma unroll
            for (int r = 0; r < 4; r++) o[dt][r] = 0.f;
        float rs0 = 0.f, rs1 = 0.f;

        const int src0 = (lane & ~3) | (tig >> 1);
        const int src1 = src0 + 2;
        const bool oddt = (tig & 1);

#pragma unroll
        for (int chunk = 0; chunk < 5; chunk++) {
            float c[5][4];
#pragma unroll
            for (int ntl = 0; ntl < 5; ntl++)
#pragma unroll
                for (int r = 0; r < 4; r++) c[ntl][r] = 0.f;

            // ---- S = Q @ K^T (fp16 m16n8k16: 4 k-chunks) ----
#pragma unroll
            for (int ntl = 0; ntl < 5; ntl++) {
                const int nt = chunk * 5 + ntl;
                const uint32_t* kb = Kh + (nt * 8 + gid) * KSTRU + tig;
#pragma unroll
                for (int kc = 0; kc < 4; kc++) {
                    uint32_t b0 = kb[kc * 8];
                    uint32_t b1 = kb[kc * 8 + 4];
                    MMA_F16(c[ntl], af[kc][0], af[kc][1], af[kc][2], af[kc][3],
                            b0, b1);
                }
            }

#pragma unroll
            for (int ntl = 0; ntl < 5; ntl++) {
                const int j0 = (chunk * 5 + ntl) * 8 + tig * 2;
                float p0 = (j0     < 197) ? __expf(c[ntl][0]) : 0.f;
                float p1 = (j0 + 1 < 197) ? __expf(c[ntl][1]) : 0.f;
                float p2 = (j0     < 197) ? __expf(c[ntl][2]) : 0.f;
                float p3 = (j0 + 1 < 197) ? __expf(c[ntl][3]) : 0.f;
                rs0 += p0 + p1;
                rs1 += p2 + p3;
                c[ntl][0] = __uint_as_float(f2tf(p0));
                c[ntl][1] = __uint_as_float(f2tf(p1));
                c[ntl][2] = __uint_as_float(f2tf(p2));
                c[ntl][3] = __uint_as_float(f2tf(p3));
            }

            // ---- O += P @ V (tf32, shuffle-P, unchanged) ----
#pragma unroll
            for (int ntl = 0; ntl < 5; ntl++) {
                const int nt = chunk * 5 + ntl;
                float x0 = __shfl_sync(0xffffffffu, c[ntl][0], src0);
                float x1 = __shfl_sync(0xffffffffu, c[ntl][1], src0);
                float x2 = __shfl_sync(0xffffffffu, c[ntl][2], src0);
                float x3 = __shfl_sync(0xffffffffu, c[ntl][3], src0);
                float y0 = __shfl_sync(0xffffffffu, c[ntl][0], src1);
                float y1 = __shfl_sync(0xffffffffu, c[ntl][1], src1);
                float y2 = __shfl_sync(0xffffffffu, c[ntl][2], src1);
                float y3 = __shfl_sync(0xffffffffu, c[ntl][3], src1);
                uint32_t a0 = __float_as_uint(oddt ? x1 : x0);
                uint32_t a1 = __float_as_uint(oddt ? x3 : x2);
                uint32_t a2 = __float_as_uint(oddt ? y1 : y0);
                uint32_t a3 = __float_as_uint(oddt ? y3 : y2);
                const uint32_t* vb = Vu + (nt * 8 + tig) * VSTR + gid;
#pragma unroll
                for (int dt = 0; dt < 8; dt++) {
                    uint32_t b0 = vb[dt * 8];
                    uint32_t b1 = vb[4 * VSTR + dt * 8];
                    MMA_TF32(o[dt], a0, a1, a2, a3, b0, b1);
                }
            }
        }

        rs0 += __shfl_xor_sync(0xffffffffu, rs0, 1);
        rs0 += __shfl_xor_sync(0xffffffffu, rs0, 2);
        rs1 += __shfl_xor_sync(0xffffffffu, rs1, 1);
        rs1 += __shfl_xor_sync(0xffffffffu, rs1, 2);
        const float inv0 = 1.f / rs0;
        const float inv1 = 1.f / rs1;

#pragma unroll
        for (int hh = 0; hh < 2; hh++) {
            int row = tile * 16 + gid + hh * 8;
            if (row < NPF) {
                float inv = hh ? inv1 : inv0;
                __half2* op = reinterpret_cast<__half2*>(
                    attn + (rowbase + 1 + fr * NPF + row) * DMODEL + hoff);
#pragma unroll
                for (int dt = 0; dt < 8; dt++)
                    op[dt * 4 + tig] = __floats2half2_rn(
                        o[dt][2 * hh] * inv, o[dt][2 * hh + 1] * inv);
            }
        }
    }
}

// ---------------- cls attention: split-K phase 1 ----------------------------
#define CLS_CH 197

__global__ __launch_bounds__(256) void cls_p1(
    const __half* __restrict__ qkh, const float* __restrict__ vsrc,
    float* __restrict__ part)
{
    const int blk  = blockIdx.x;          // (b*NH + h)*8 + c
    const int c    = blk & 7;
    const int bh   = blk >> 3;
    const int b    = bh / NH;
    const int h    = bh % NH;
    const int tid  = threadIdx.x;
    const int warp = tid >> 5, lane = tid & 31;

    __shared__ float qs[64];
    __shared__ float wacc[8][64];
    __shared__ float wl[8];

    const long rowbase = (long)b * NSEQ;
    const int  hoff    = h * DH;

    if (tid < 64)
        qs[tid] = __half2float(qkh[rowbase * QKH_W + hoff + tid]) * 0.125f;
    __syncthreads();

    const int j0 = c * CLS_CH;
    const int jn = (j0 + CLS_CH <= NSEQ) ? CLS_CH : (NSEQ - j0);

    const float q0 = qs[lane * 2];
    const float q1 = qs[lane * 2 + 1];

    float a0 = 0.f, a1 = 0.f, l = 0.f;

    for (int jj = warp; jj < jn; jj += 8) {
        const long r = rowbase + j0 + jj;
        __half2 kk = *reinterpret_cast<const __half2*>(
            qkh + r * QKH_W + DMODEL + hoff + lane * 2);
        float2 kf = __half22float2(kk);
        float s = q0 * kf.x + q1 * kf.y;
#pragma unroll
        for (int off = 16; off; off >>= 1)
            s += __shfl_xor_sync(0xffffffffu, s, off);
        float p = __expf(s);
        l += p;
        float2 vv = *reinterpret_cast<const float2*>(
            vsrc + r * DMODEL + hoff + lane * 2);
        a0 = fmaf(p, vv.x, a0);
        a1 = fmaf(p, vv.y, a1);
    }

    wacc[warp][lane * 2]     = a0;
    wacc[warp][lane * 2 + 1] = a1;
    if (lane == 0) wl[warp] = l;
    __syncthreads();

    if (tid < 64) {
        float s = 0.f;
#pragma unroll
        for (int w = 0; w < 8; w++) s += wacc[w][tid];
        part[(size_t)blk * 65 + tid] = s;
        if (tid == 0) {
            float lt = 0.f;
#pragma unroll
            for (int w = 0; w < 8; w++) lt += wl[w];
            part[(size_t)blk * 65 + 64] = lt;
        }
    }
}

// ---------------- cls attention: split-K phase 2 ----------------------------
__global__ __launch_bounds__(64) void cls_p2(
    const float* __restrict__ part, __half* __restrict__ attn)
{
    const int bh = blockIdx.x;
    const int b  = bh / NH;
    const int h  = bh % NH;
    const int d  = threadIdx.x;

    float s = 0.f, lt = 0.f;
#pragma unroll
    for (int c = 0; c < 8; c++) {
        s  += part[(size_t)(bh * 8 + c) * 65 + d];
        lt += part[(size_t)(bh * 8 + c) * 65 + 64];
    }
    attn[(long)b * NSEQ * DMODEL + h * DH + d] = __float2half(s / lt);
}

// ---------------- host launch ----------------------------------------------
extern "C" void kernel_launch(void* const* d_in, const int* in_sizes, int n_in,
                              void* d_out, int out_size)
{
    const float* x      = (const float*)d_in[0];
    const float* w_qkv  = (const float*)d_in[1];
    const float* w_proj = (const float*)d_in[2];
    const float* b_proj = (const float*)d_in[3];
    float* out = (float*)d_out;

    float *vbuf, *clsp;
    __half *qkh, *attnh, *xh, *wqh, *wph;
    cudaGetSymbolAddress((void**)&qkh,   g_qkh);
    cudaGetSymbolAddress((void**)&vbuf,  g_v);
    cudaGetSymbolAddress((void**)&attnh, g_attnh);
    cudaGetSymbolAddress((void**)&xh,    g_xh);
    cudaGetSymbolAddress((void**)&wqh,   g_wqh);
    cudaGetSymbolAddress((void**)&wph,   g_wph);
    cudaGetSymbolAddress((void**)&clsp,  g_cls);

    cudaFuncSetAttribute((const void*)gemm_f16<0>,
                         cudaFuncAttributeMaxDynamicSharedMemorySize, GEMM_SMEM);
    cudaFuncSetAttribute((const void*)gemm_f16<1>,
                         cudaFuncAttributeMaxDynamicSharedMemorySize, GEMM_SMEM);
    cudaFuncSetAttribute(frame_attn_mma,
                         cudaFuncAttributeMaxDynamicSharedMemorySize, F_SMEM);

    // prep
    prep_x<<<(N4X + 255) / 256, 256>>>(x, xh);
    transpose_h<<<dim3(QKVC / 32, DMODEL / 32), 256>>>(w_qkv, wqh, DMODEL, QKVC);
    transpose_h<<<dim3(DMODEL / 32, DMODEL / 32), 256>>>(w_proj, wph, DMODEL, DMODEL);

    const int mtiles = (MROWS + BM - 1) / BM;   // 197

    // qkv GEMM: split epilogue (Q,K fp16; V fp32 tf32-rounded)
    gemm_f16<1><<<dim3(QKVC / BN, mtiles), 256, GEMM_SMEM>>>(
        xh, wqh, nullptr, nullptr, qkh, vbuf, MROWS, QKVC, DMODEL);

    cls_p1<<<Bq * NH * 8, 256>>>(qkh, vbuf, clsp);
    frame_attn_mma<<<Bq * NH * NF * 2, 256, F_SMEM>>>(qkh, vbuf, attnh);
    cls_p2<<<Bq * NH, 64>>>(clsp, attnh);

    // proj GEMM: fp32 out + bias
    gemm_f16<0><<<dim3(DMODEL / BN, mtiles), 256, GEMM_SMEM>>>(
        attnh, wph, b_proj, out, nullptr, nullptr, MROWS, DMODEL, DMODEL);
}